// round 1
// baseline (speedup 1.0000x reference)
#include <cuda_runtime.h>
#include <math.h>

#define NN   8192
#define BB   8
#define LL   1024
#define INC  64
#define HH   8
#define CC   32
#define DD   256
#define DFF  2048
#define EMAX 262144
#define ETOTMAX (EMAX + NN)

// ---------------- scratch (device globals; no runtime allocation) ----------------
__device__ float g_hl  [NN * DD];
__device__ float g_h0  [NN * DD];
__device__ float g_h1  [NN * DD];
__device__ float g_as  [NN * HH];
__device__ float g_ad  [NN * HH];
__device__ float g_m   [NN * HH];
__device__ float g_ss  [NN * HH];
__device__ float g_e   [ETOTMAX * HH];
__device__ float g_qkv [NN * 3 * DD];
__device__ float g_attn[NN * DD];
__device__ float g_tmp [NN * DD];
__device__ float g_ff  [NN * DFF];

// ---------------- helpers ----------------
__device__ __forceinline__ void atomicMaxF(float* a, float v) {
    if (v >= 0.0f) atomicMax((int*)a, __float_as_int(v));
    else           atomicMin((unsigned int*)a, __float_as_uint(v));
}

__device__ __forceinline__ void redAdd4(float* p, float a, float b, float c, float d) {
    asm volatile("red.global.add.v4.f32 [%0], {%1,%2,%3,%4};"
                 :: "l"(p), "f"(a), "f"(b), "f"(c), "f"(d) : "memory");
}

// ---------------- SGEMM: C[M,Nn] = A[M,K] * W[Nn,K]^T (+bias)(+relu) ----------------
// BIASMODE: 0 = none, 1 = bias, 2 = bias+relu
template<int BIASMODE>
__global__ void __launch_bounds__(256) sgemm_kernel(
    const float* __restrict__ A, const float* __restrict__ W,
    const float* __restrict__ bias, float* __restrict__ C,
    int M, int Nn, int K)
{
    __shared__ float As[16][68];
    __shared__ float Bs[16][68];
    const int bm = blockIdx.y * 64;
    const int bn = blockIdx.x * 64;
    const int tid = threadIdx.x;
    const int lk = tid & 15, lr = tid >> 4;   // load mapping
    const int tx = tid & 15, ty = tid >> 4;   // compute mapping

    float acc[4][4];
#pragma unroll
    for (int i = 0; i < 4; i++)
#pragma unroll
        for (int j = 0; j < 4; j++) acc[i][j] = 0.0f;

    for (int k0 = 0; k0 < K; k0 += 16) {
#pragma unroll
        for (int i = 0; i < 4; i++) {
            int m = lr + i * 16;
            As[lk][m] = A[(size_t)(bm + m) * K + k0 + lk];
            Bs[lk][m] = W[(size_t)(bn + m) * K + k0 + lk];
        }
        __syncthreads();
#pragma unroll
        for (int k = 0; k < 16; k++) {
            float4 av = *reinterpret_cast<const float4*>(&As[k][ty * 4]);
            float4 bv = *reinterpret_cast<const float4*>(&Bs[k][tx * 4]);
            float aa[4] = {av.x, av.y, av.z, av.w};
            float bb[4] = {bv.x, bv.y, bv.z, bv.w};
#pragma unroll
            for (int i = 0; i < 4; i++)
#pragma unroll
                for (int j = 0; j < 4; j++) acc[i][j] += aa[i] * bb[j];
        }
        __syncthreads();
    }

    float4 bvv = make_float4(0.f, 0.f, 0.f, 0.f);
    if (BIASMODE > 0) bvv = *reinterpret_cast<const float4*>(&bias[bn + tx * 4]);
#pragma unroll
    for (int i = 0; i < 4; i++) {
        int row = bm + ty * 4 + i;
        float4 o;
        o.x = acc[i][0] + bvv.x;
        o.y = acc[i][1] + bvv.y;
        o.z = acc[i][2] + bvv.z;
        o.w = acc[i][3] + bvv.w;
        if (BIASMODE == 2) {
            o.x = fmaxf(o.x, 0.f); o.y = fmaxf(o.y, 0.f);
            o.z = fmaxf(o.z, 0.f); o.w = fmaxf(o.w, 0.f);
        }
        *reinterpret_cast<float4*>(&C[(size_t)row * Nn + bn + tx * 4]) = o;
    }
}

// ---------------- GAT kernels ----------------
__global__ void gat_coef_kernel(const float* __restrict__ hl,
                                const float* __restrict__ atts,
                                const float* __restrict__ attd,
                                float* __restrict__ as_, float* __restrict__ ad_)
{
    int t = blockIdx.x * blockDim.x + threadIdx.x;
    if (t >= NN * HH) return;
    int n = t >> 3, h = t & 7;
    const float4* hp = reinterpret_cast<const float4*>(&hl[(size_t)n * DD + h * 32]);
    const float4* sp = reinterpret_cast<const float4*>(&atts[h * 32]);
    const float4* dp = reinterpret_cast<const float4*>(&attd[h * 32]);
    float ss = 0.f, dd = 0.f;
#pragma unroll
    for (int w = 0; w < 8; w++) {
        float4 hv = hp[w], sv = sp[w], dv = dp[w];
        ss += hv.x * sv.x + hv.y * sv.y + hv.z * sv.z + hv.w * sv.w;
        dd += hv.x * dv.x + hv.y * dv.y + hv.z * dv.z + hv.w * dv.w;
    }
    as_[t] = ss;
    ad_[t] = dd;
}

__global__ void gat_init_kernel(float* __restrict__ out, float* __restrict__ m,
                                float* __restrict__ s)
{
    int i = blockIdx.x * blockDim.x + threadIdx.x;
    if (i < NN * DD) out[i] = 0.0f;
    if (i < NN * HH) { m[i] = -1e30f; s[i] = 0.0f; }
}

__global__ void gat_edge_max_kernel(const int* __restrict__ src, const int* __restrict__ dst,
                                    int E, int Etot,
                                    const float* __restrict__ as_, const float* __restrict__ ad_,
                                    float* __restrict__ ebuf, float* __restrict__ m)
{
    int e = blockIdx.x * blockDim.x + threadIdx.x;
    if (e >= Etot) return;
    int s, d;
    if (e < E) { s = src[e]; d = dst[e]; } else { s = d = e - E; }
    float4 s0 = *reinterpret_cast<const float4*>(&as_[s * 8]);
    float4 s1 = *reinterpret_cast<const float4*>(&as_[s * 8 + 4]);
    float4 d0 = *reinterpret_cast<const float4*>(&ad_[d * 8]);
    float4 d1 = *reinterpret_cast<const float4*>(&ad_[d * 8 + 4]);
    float ev[8] = {s0.x + d0.x, s0.y + d0.y, s0.z + d0.z, s0.w + d0.w,
                   s1.x + d1.x, s1.y + d1.y, s1.z + d1.z, s1.w + d1.w};
#pragma unroll
    for (int h = 0; h < 8; h++) {
        float t = ev[h];
        t = (t > 0.f) ? t : 0.2f * t;
        ev[h] = t;
        atomicMaxF(&m[d * 8 + h], t);
    }
    *reinterpret_cast<float4*>(&ebuf[(size_t)e * 8])     = make_float4(ev[0], ev[1], ev[2], ev[3]);
    *reinterpret_cast<float4*>(&ebuf[(size_t)e * 8 + 4]) = make_float4(ev[4], ev[5], ev[6], ev[7]);
}

__global__ void gat_edge_exp_kernel(const int* __restrict__ dst, int E, int Etot,
                                    float* __restrict__ ebuf,
                                    const float* __restrict__ m, float* __restrict__ ssum)
{
    int e = blockIdx.x * blockDim.x + threadIdx.x;
    if (e >= Etot) return;
    int d = (e < E) ? dst[e] : (e - E);
    float4 e0 = *reinterpret_cast<const float4*>(&ebuf[(size_t)e * 8]);
    float4 e1 = *reinterpret_cast<const float4*>(&ebuf[(size_t)e * 8 + 4]);
    float4 m0 = *reinterpret_cast<const float4*>(&m[d * 8]);
    float4 m1 = *reinterpret_cast<const float4*>(&m[d * 8 + 4]);
    float ee[8] = {__expf(e0.x - m0.x), __expf(e0.y - m0.y), __expf(e0.z - m0.z), __expf(e0.w - m0.w),
                   __expf(e1.x - m1.x), __expf(e1.y - m1.y), __expf(e1.z - m1.z), __expf(e1.w - m1.w)};
#pragma unroll
    for (int h = 0; h < 8; h++) atomicAdd(&ssum[d * 8 + h], ee[h]);
    *reinterpret_cast<float4*>(&ebuf[(size_t)e * 8])     = make_float4(ee[0], ee[1], ee[2], ee[3]);
    *reinterpret_cast<float4*>(&ebuf[(size_t)e * 8 + 4]) = make_float4(ee[4], ee[5], ee[6], ee[7]);
}

__global__ void gat_agg_kernel(const int* __restrict__ src, const int* __restrict__ dst,
                               int E, int Etot,
                               const float* __restrict__ ebuf, const float* __restrict__ ssum,
                               const float* __restrict__ hl, float* __restrict__ out)
{
    int idx = blockIdx.x * blockDim.x + threadIdx.x;
    if (idx >= Etot * 8) return;
    int e = idx >> 3, h = idx & 7;
    int s, d;
    if (e < E) { s = src[e]; d = dst[e]; } else { s = d = e - E; }
    float alpha = ebuf[idx] / ssum[d * 8 + h];
    const float4* hs = reinterpret_cast<const float4*>(&hl[(size_t)s * DD + h * 32]);
    float* op = &out[(size_t)d * DD + h * 32];
#pragma unroll
    for (int w = 0; w < 8; w++) {
        float4 hv = hs[w];
        redAdd4(op + w * 4, hv.x * alpha, hv.y * alpha, hv.z * alpha, hv.w * alpha);
    }
}

__global__ void bias_relu_kernel(float* __restrict__ out, const float* __restrict__ bias)
{
    int i = blockIdx.x * blockDim.x + threadIdx.x;
    if (i >= NN * DD) return;
    out[i] = fmaxf(out[i] + bias[i & 255], 0.0f);
}

// ---------------- attention (flash-style, warp per query) ----------------
__global__ void __launch_bounds__(512) attn_kernel(const float* __restrict__ qkv,
                                                   float* __restrict__ out)
{
    const int bh = blockIdx.x;          // 0..63
    const int b = bh >> 3, h = bh & 7;
    const int warp = threadIdx.x >> 5, lane = threadIdx.x & 31;
    const int q = blockIdx.y * 16 + warp;
    const float* base = qkv + (size_t)b * LL * 768;

    float qv[32];
    const float* qp = base + q * 768 + h * 32;
#pragma unroll
    for (int c = 0; c < 32; c++) qv[c] = qp[c] * 0.17677669529663687f; // 1/sqrt(32)

    __shared__ float Ks[128 * 36];
    __shared__ float Vs[128 * 36];

    float m = -1e30f, s = 0.f;
    float acc[32];
#pragma unroll
    for (int c = 0; c < 32; c++) acc[c] = 0.f;

    for (int t = 0; t < 8; t++) {
        __syncthreads();
#pragma unroll
        for (int i = 0; i < 8; i++) {
            int e2 = threadIdx.x + i * 512;
            int row = e2 >> 5, col = e2 & 31;
            const float* kp = base + (t * 128 + row) * 768 + 256 + h * 32 + col;
            Ks[row * 36 + col] = kp[0];
            Vs[row * 36 + col] = kp[256];
        }
        __syncthreads();
#pragma unroll
        for (int jj = 0; jj < 4; jj++) {
            int j = jj * 32 + lane;
            const float4* kr = reinterpret_cast<const float4*>(&Ks[j * 36]);
            float sc = 0.f;
#pragma unroll
            for (int w = 0; w < 8; w++) {
                float4 kk = kr[w];
                sc += qv[4 * w + 0] * kk.x + qv[4 * w + 1] * kk.y
                    + qv[4 * w + 2] * kk.z + qv[4 * w + 3] * kk.w;
            }
            float mn = fmaxf(m, sc);
            float corr = __expf(m - mn);
            float p = __expf(sc - mn);
            s = s * corr + p;
            const float4* vr = reinterpret_cast<const float4*>(&Vs[j * 36]);
#pragma unroll
            for (int w = 0; w < 8; w++) {
                float4 vv = vr[w];
                acc[4 * w + 0] = acc[4 * w + 0] * corr + p * vv.x;
                acc[4 * w + 1] = acc[4 * w + 1] * corr + p * vv.y;
                acc[4 * w + 2] = acc[4 * w + 2] * corr + p * vv.z;
                acc[4 * w + 3] = acc[4 * w + 3] * corr + p * vv.w;
            }
            m = mn;
        }
    }

    // merge across lanes
    float M = m;
#pragma unroll
    for (int o = 16; o; o >>= 1) M = fmaxf(M, __shfl_xor_sync(0xffffffffu, M, o));
    float f = __expf(m - M);
    float st = s * f;
#pragma unroll
    for (int o = 16; o; o >>= 1) st += __shfl_xor_sync(0xffffffffu, st, o);
    float inv = 1.0f / st;

    float oc = 0.f;
#pragma unroll
    for (int c = 0; c < 32; c++) {
        float v = acc[c] * f;
#pragma unroll
        for (int o = 16; o; o >>= 1) v += __shfl_xor_sync(0xffffffffu, v, o);
        if (lane == c) oc = v;
    }
    out[(size_t)(b * LL + q) * DD + h * 32 + lane] = oc * inv;
}

// ---------------- residual + LayerNorm ----------------
__global__ void __launch_bounds__(256) ln_res_kernel(
    const float* __restrict__ x, const float* __restrict__ r,
    const float* __restrict__ w, const float* __restrict__ b,
    float* __restrict__ y)
{
    int row = blockIdx.x, t = threadIdx.x;
    size_t i = (size_t)row * DD + t;
    float v = x[i] + r[i];
    float s1 = v, s2 = v * v;
#pragma unroll
    for (int o = 16; o; o >>= 1) {
        s1 += __shfl_xor_sync(0xffffffffu, s1, o);
        s2 += __shfl_xor_sync(0xffffffffu, s2, o);
    }
    __shared__ float a1[8], a2[8];
    int wid = t >> 5, lane = t & 31;
    if (lane == 0) { a1[wid] = s1; a2[wid] = s2; }
    __syncthreads();
    float S1 = 0.f, S2 = 0.f;
#pragma unroll
    for (int k = 0; k < 8; k++) { S1 += a1[k]; S2 += a2[k]; }
    float mu = S1 * (1.0f / DD);
    float var = S2 * (1.0f / DD) - mu * mu;
    y[i] = (v - mu) * rsqrtf(var + 1e-5f) * w[t] + b[t];
}

// ---------------- final prediction ----------------
__global__ void __launch_bounds__(256) pred_kernel(
    const float* __restrict__ x, const float* __restrict__ pw,
    const float* __restrict__ pb, float* __restrict__ out)
{
    int n = blockIdx.x * 8 + (threadIdx.x >> 5);
    int lane = threadIdx.x & 31;
    const float* xr = x + (size_t)n * DD;
    float xv[8];
#pragma unroll
    for (int k = 0; k < 8; k++) xv[k] = xr[lane + 32 * k];
    float a0 = 0.f, a1 = 0.f, a2 = 0.f;
#pragma unroll
    for (int k = 0; k < 8; k++) {
        int c = lane + 32 * k;
        a0 += xv[k] * pw[0 * DD + c];
        a1 += xv[k] * pw[1 * DD + c];
        a2 += xv[k] * pw[2 * DD + c];
    }
#pragma unroll
    for (int o = 16; o; o >>= 1) {
        a0 += __shfl_xor_sync(0xffffffffu, a0, o);
        a1 += __shfl_xor_sync(0xffffffffu, a1, o);
        a2 += __shfl_xor_sync(0xffffffffu, a2, o);
    }
    if (lane == 0) {
        out[n * 3 + 0] = a0 + pb[0];
        out[n * 3 + 1] = a1 + pb[1];
        out[n * 3 + 2] = a2 + pb[2];
    }
}

// ---------------- host orchestration ----------------
extern "C" void kernel_launch(void* const* d_in, const int* in_sizes, int n_in,
                              void* d_out, int out_size)
{
    const float* x        = (const float*)d_in[0];
    const int*   ei       = (const int*)  d_in[1];
    const float* gat_W0   = (const float*)d_in[3];
    const float* gat_W12  = (const float*)d_in[4];
    const float* att_src  = (const float*)d_in[5];
    const float* att_dst  = (const float*)d_in[6];
    const float* gat_bias = (const float*)d_in[7];
    const float* qkv_w    = (const float*)d_in[8];
    const float* qkv_b    = (const float*)d_in[9];
    const float* out_w    = (const float*)d_in[10];
    const float* out_b    = (const float*)d_in[11];
    const float* ln1_w    = (const float*)d_in[12];
    const float* ln1_b    = (const float*)d_in[13];
    const float* ln2_w    = (const float*)d_in[14];
    const float* ln2_b    = (const float*)d_in[15];
    const float* ff1_w    = (const float*)d_in[16];
    const float* ff1_b    = (const float*)d_in[17];
    const float* ff2_w    = (const float*)d_in[18];
    const float* ff2_b    = (const float*)d_in[19];
    const float* pred_w   = (const float*)d_in[20];
    const float* pred_b   = (const float*)d_in[21];

    const int E = in_sizes[1] / 2;
    const int Etot = E + NN;
    const int* src = ei;
    const int* dst = ei + E;

    float *hl, *h0, *h1, *as_, *ad_, *m_, *ss_, *e_, *qkv, *attn, *tmp, *ff;
    cudaGetSymbolAddress((void**)&hl,   g_hl);
    cudaGetSymbolAddress((void**)&h0,   g_h0);
    cudaGetSymbolAddress((void**)&h1,   g_h1);
    cudaGetSymbolAddress((void**)&as_,  g_as);
    cudaGetSymbolAddress((void**)&ad_,  g_ad);
    cudaGetSymbolAddress((void**)&m_,   g_m);
    cudaGetSymbolAddress((void**)&ss_,  g_ss);
    cudaGetSymbolAddress((void**)&e_,   g_e);
    cudaGetSymbolAddress((void**)&qkv,  g_qkv);
    cudaGetSymbolAddress((void**)&attn, g_attn);
    cudaGetSymbolAddress((void**)&tmp,  g_tmp);
    cudaGetSymbolAddress((void**)&ff,   g_ff);

    const int eb = (Etot + 255) / 256;

    auto gat_layer = [&](const float* in, int Din, const float* W,
                         const float* atts, const float* attd, const float* bias,
                         float* outp) {
        sgemm_kernel<0><<<dim3(DD / 64, NN / 64), 256>>>(in, W, nullptr, hl, NN, DD, Din);
        gat_coef_kernel<<<(NN * HH) / 256, 256>>>(hl, atts, attd, as_, ad_);
        gat_init_kernel<<<(NN * DD) / 256, 256>>>(outp, m_, ss_);
        gat_edge_max_kernel<<<eb, 256>>>(src, dst, E, Etot, as_, ad_, e_, m_);
        gat_edge_exp_kernel<<<eb, 256>>>(dst, E, Etot, e_, m_, ss_);
        gat_agg_kernel<<<(Etot * 8 + 255) / 256, 256>>>(src, dst, E, Etot, e_, ss_, hl, outp);
        bias_relu_kernel<<<(NN * DD) / 256, 256>>>(outp, bias);
    };

    gat_layer(x,  INC, gat_W0,            att_src,           att_dst,           gat_bias,          h0);
    gat_layer(h0, DD,  gat_W12,           att_src + HH * CC, att_dst + HH * CC, gat_bias + DD,     h1);
    gat_layer(h1, DD,  gat_W12 + DD * DD, att_src + 2*HH*CC, att_dst + 2*HH*CC, gat_bias + 2 * DD, h0);

    for (int l = 0; l < 2; l++) {
        const float* qw  = qkv_w + (size_t)l * 3 * DD * DD;
        const float* qb  = qkv_b + l * 3 * DD;
        const float* ow  = out_w + (size_t)l * DD * DD;
        const float* ob  = out_b + l * DD;
        const float* l1w = ln1_w + l * DD, * l1b = ln1_b + l * DD;
        const float* l2w = ln2_w + l * DD, * l2b = ln2_b + l * DD;
        const float* f1w = ff1_w + (size_t)l * DFF * DD;
        const float* f1b = ff1_b + l * DFF;
        const float* f2w = ff2_w + (size_t)l * DD * DFF;
        const float* f2b = ff2_b + l * DD;

        sgemm_kernel<1><<<dim3(3 * DD / 64, NN / 64), 256>>>(h0, qw, qb, qkv, NN, 3 * DD, DD);
        attn_kernel<<<dim3(BB * HH, LL / 16), 512>>>(qkv, attn);
        sgemm_kernel<1><<<dim3(DD / 64, NN / 64), 256>>>(attn, ow, ob, tmp, NN, DD, DD);
        ln_res_kernel<<<NN, 256>>>(h0, tmp, l1w, l1b, h1);
        sgemm_kernel<2><<<dim3(DFF / 64, NN / 64), 256>>>(h1, f1w, f1b, ff, NN, DFF, DD);
        sgemm_kernel<1><<<dim3(DD / 64, NN / 64), 256>>>(ff, f2w, f2b, tmp, NN, DD, DFF);
        ln_res_kernel<<<NN, 256>>>(h1, tmp, l2w, l2b, h0);
    }

    pred_kernel<<<NN / 8, 256>>>(h0, pred_w, pred_b, (float*)d_out);
}

// round 2
// speedup vs baseline: 1.5791x; 1.5791x over previous
#include <cuda_runtime.h>
#include <math.h>

#define NN   8192
#define BB   8
#define LL   1024
#define INC  64
#define HH   8
#define CC   32
#define DD   256
#define DFF  2048
#define EMAX 262144
#define ETOTMAX (EMAX + NN)

// ---------------- scratch (device globals; no runtime allocation) ----------------
__device__ float g_hl  [NN * DD];
__device__ float g_h0  [NN * DD];
__device__ float g_h1  [NN * DD];
__device__ float g_as  [NN * HH];
__device__ float g_ad  [NN * HH];
__device__ float g_m   [NN * HH];
__device__ float g_ss  [NN * HH];
__device__ float g_e   [ETOTMAX * HH];
__device__ float g_qkv [NN * 3 * DD];
__device__ float g_attn[NN * DD];
__device__ float g_tmp [NN * DD];
__device__ float g_ff  [NN * DFF];

// ---------------- helpers ----------------
__device__ __forceinline__ void atomicMaxF(float* a, float v) {
    if (v >= 0.0f) atomicMax((int*)a, __float_as_int(v));
    else           atomicMin((unsigned int*)a, __float_as_uint(v));
}

__device__ __forceinline__ void redAdd4(float* p, float a, float b, float c, float d) {
    asm volatile("red.global.add.v4.f32 [%0], {%1,%2,%3,%4};"
                 :: "l"(p), "f"(a), "f"(b), "f"(c), "f"(d) : "memory");
}

__device__ __forceinline__ unsigned f2tf(float f) {
    unsigned u;
    asm("cvt.rna.tf32.f32 %0, %1;" : "=r"(u) : "f"(f));
    return u;
}

__device__ __forceinline__ void f2tf_split(float f, unsigned& hi, unsigned& lo) {
    hi = f2tf(f);
    lo = f2tf(f - __uint_as_float(hi));
}

__device__ __forceinline__ void mma8(float* d, const unsigned* a, const unsigned* b) {
    asm volatile(
        "mma.sync.aligned.m16n8k8.row.col.f32.tf32.tf32.f32 "
        "{%0,%1,%2,%3},{%4,%5,%6,%7},{%8,%9},{%0,%1,%2,%3};"
        : "+f"(d[0]), "+f"(d[1]), "+f"(d[2]), "+f"(d[3])
        : "r"(a[0]), "r"(a[1]), "r"(a[2]), "r"(a[3]), "r"(b[0]), "r"(b[1]));
}

// ---------------- tensor-core GEMM: C[M,Nn] = A[M,K] * W[Nn,K]^T (+bias)(+relu) ----
// tf32 with A split into hi+lo (2-pass) for fp32-grade accuracy.
// BM=128, BN=128, BK=32; 8 warps = 4(m) x 2(n); warp tile 32m x 64n.
// Requires: M%128==0, Nn%128==0, K%32==0.
template<int BIASMODE>
__global__ void __launch_bounds__(256) tgemm_kernel(
    const float* __restrict__ A, const float* __restrict__ W,
    const float* __restrict__ bias, float* __restrict__ C,
    int M, int Nn, int K)
{
    __shared__ __align__(16) float As[128][36];
    __shared__ __align__(16) float Bs[128][36];
    const int bm = blockIdx.y * 128;
    const int bn = blockIdx.x * 128;
    const int tid = threadIdx.x;
    const int warp = tid >> 5, lane = tid & 31;
    const int wm = warp & 3, wn = warp >> 2;
    const int lg = lane >> 2;       // group id 0..7
    const int lt = lane & 3;        // thread-in-group 0..3

    float acc[2][8][4];
#pragma unroll
    for (int mt = 0; mt < 2; mt++)
#pragma unroll
        for (int nt = 0; nt < 8; nt++)
#pragma unroll
            for (int r = 0; r < 4; r++) acc[mt][nt][r] = 0.0f;

    for (int k0 = 0; k0 < K; k0 += 32) {
#pragma unroll
        for (int i = 0; i < 4; i++) {
            int f4 = tid + i * 256;              // 0..1023
            int row = f4 >> 3, c4 = (f4 & 7) << 2;
            *(float4*)&As[row][c4] = *(const float4*)&A[(size_t)(bm + row) * K + k0 + c4];
            *(float4*)&Bs[row][c4] = *(const float4*)&W[(size_t)(bn + row) * K + k0 + c4];
        }
        __syncthreads();
#pragma unroll
        for (int kk = 0; kk < 32; kk += 8) {
            unsigned ah[2][4], al[2][4], bf[8][2];
            const int c = kk + lt;
#pragma unroll
            for (int mt = 0; mt < 2; mt++) {
                int r = wm * 32 + mt * 16 + lg;
                f2tf_split(As[r][c],         ah[mt][0], al[mt][0]);
                f2tf_split(As[r + 8][c],     ah[mt][1], al[mt][1]);
                f2tf_split(As[r][c + 4],     ah[mt][2], al[mt][2]);
                f2tf_split(As[r + 8][c + 4], ah[mt][3], al[mt][3]);
            }
#pragma unroll
            for (int nt = 0; nt < 8; nt++) {
                int n = wn * 64 + nt * 8 + lg;
                bf[nt][0] = f2tf(Bs[n][c]);
                bf[nt][1] = f2tf(Bs[n][c + 4]);
            }
#pragma unroll
            for (int mt = 0; mt < 2; mt++)
#pragma unroll
                for (int nt = 0; nt < 8; nt++) {
                    mma8(acc[mt][nt], ah[mt], bf[nt]);
                    mma8(acc[mt][nt], al[mt], bf[nt]);
                }
        }
        __syncthreads();
    }

#pragma unroll
    for (int mt = 0; mt < 2; mt++) {
#pragma unroll
        for (int nt = 0; nt < 8; nt++) {
            int row = bm + wm * 32 + mt * 16 + lg;
            int col = bn + wn * 64 + nt * 8 + (lt << 1);
            float b0 = 0.f, b1 = 0.f;
            if (BIASMODE > 0) { b0 = bias[col]; b1 = bias[col + 1]; }
            float v0 = acc[mt][nt][0] + b0, v1 = acc[mt][nt][1] + b1;
            float v2 = acc[mt][nt][2] + b0, v3 = acc[mt][nt][3] + b1;
            if (BIASMODE == 2) {
                v0 = fmaxf(v0, 0.f); v1 = fmaxf(v1, 0.f);
                v2 = fmaxf(v2, 0.f); v3 = fmaxf(v3, 0.f);
            }
            float2 o0 = make_float2(v0, v1), o1 = make_float2(v2, v3);
            *(float2*)&C[(size_t)row * Nn + col] = o0;
            *(float2*)&C[(size_t)(row + 8) * Nn + col] = o1;
        }
    }
}

// ---------------- GAT kernels ----------------
__global__ void gat_coef_kernel(const float* __restrict__ hl,
                                const float* __restrict__ atts,
                                const float* __restrict__ attd,
                                float* __restrict__ as_, float* __restrict__ ad_)
{
    int t = blockIdx.x * blockDim.x + threadIdx.x;
    if (t >= NN * HH) return;
    int n = t >> 3, h = t & 7;
    const float4* hp = reinterpret_cast<const float4*>(&hl[(size_t)n * DD + h * 32]);
    const float4* sp = reinterpret_cast<const float4*>(&atts[h * 32]);
    const float4* dp = reinterpret_cast<const float4*>(&attd[h * 32]);
    float ss = 0.f, dd = 0.f;
#pragma unroll
    for (int w = 0; w < 8; w++) {
        float4 hv = hp[w], sv = sp[w], dv = dp[w];
        ss += hv.x * sv.x + hv.y * sv.y + hv.z * sv.z + hv.w * sv.w;
        dd += hv.x * dv.x + hv.y * dv.y + hv.z * dv.z + hv.w * dv.w;
    }
    as_[t] = ss;
    ad_[t] = dd;
}

__global__ void gat_init_kernel(float* __restrict__ out, float* __restrict__ m,
                                float* __restrict__ s)
{
    int i = blockIdx.x * blockDim.x + threadIdx.x;
    if (i < NN * DD) out[i] = 0.0f;
    if (i < NN * HH) { m[i] = -1e30f; s[i] = 0.0f; }
}

__global__ void gat_edge_max_kernel(const int* __restrict__ src, const int* __restrict__ dst,
                                    int E, int Etot,
                                    const float* __restrict__ as_, const float* __restrict__ ad_,
                                    float* __restrict__ ebuf, float* __restrict__ m)
{
    int e = blockIdx.x * blockDim.x + threadIdx.x;
    if (e >= Etot) return;
    int s, d;
    if (e < E) { s = src[e]; d = dst[e]; } else { s = d = e - E; }
    float4 s0 = *reinterpret_cast<const float4*>(&as_[s * 8]);
    float4 s1 = *reinterpret_cast<const float4*>(&as_[s * 8 + 4]);
    float4 d0 = *reinterpret_cast<const float4*>(&ad_[d * 8]);
    float4 d1 = *reinterpret_cast<const float4*>(&ad_[d * 8 + 4]);
    float ev[8] = {s0.x + d0.x, s0.y + d0.y, s0.z + d0.z, s0.w + d0.w,
                   s1.x + d1.x, s1.y + d1.y, s1.z + d1.z, s1.w + d1.w};
#pragma unroll
    for (int h = 0; h < 8; h++) {
        float t = ev[h];
        t = (t > 0.f) ? t : 0.2f * t;
        ev[h] = t;
        atomicMaxF(&m[d * 8 + h], t);
    }
    *reinterpret_cast<float4*>(&ebuf[(size_t)e * 8])     = make_float4(ev[0], ev[1], ev[2], ev[3]);
    *reinterpret_cast<float4*>(&ebuf[(size_t)e * 8 + 4]) = make_float4(ev[4], ev[5], ev[6], ev[7]);
}

__global__ void gat_edge_exp_kernel(const int* __restrict__ dst, int E, int Etot,
                                    float* __restrict__ ebuf,
                                    const float* __restrict__ m, float* __restrict__ ssum)
{
    int e = blockIdx.x * blockDim.x + threadIdx.x;
    if (e >= Etot) return;
    int d = (e < E) ? dst[e] : (e - E);
    float4 e0 = *reinterpret_cast<const float4*>(&ebuf[(size_t)e * 8]);
    float4 e1 = *reinterpret_cast<const float4*>(&ebuf[(size_t)e * 8 + 4]);
    float4 m0 = *reinterpret_cast<const float4*>(&m[d * 8]);
    float4 m1 = *reinterpret_cast<const float4*>(&m[d * 8 + 4]);
    float ee[8] = {__expf(e0.x - m0.x), __expf(e0.y - m0.y), __expf(e0.z - m0.z), __expf(e0.w - m0.w),
                   __expf(e1.x - m1.x), __expf(e1.y - m1.y), __expf(e1.z - m1.z), __expf(e1.w - m1.w)};
#pragma unroll
    for (int h = 0; h < 8; h++) atomicAdd(&ssum[d * 8 + h], ee[h]);
    *reinterpret_cast<float4*>(&ebuf[(size_t)e * 8])     = make_float4(ee[0], ee[1], ee[2], ee[3]);
    *reinterpret_cast<float4*>(&ebuf[(size_t)e * 8 + 4]) = make_float4(ee[4], ee[5], ee[6], ee[7]);
}

__global__ void gat_agg_kernel(const int* __restrict__ src, const int* __restrict__ dst,
                               int E, int Etot,
                               const float* __restrict__ ebuf, const float* __restrict__ ssum,
                               const float* __restrict__ hl, float* __restrict__ out)
{
    int idx = blockIdx.x * blockDim.x + threadIdx.x;
    if (idx >= Etot * 8) return;
    int e = idx >> 3, h = idx & 7;
    int s, d;
    if (e < E) { s = src[e]; d = dst[e]; } else { s = d = e - E; }
    float alpha = ebuf[idx] / ssum[d * 8 + h];
    const float4* hs = reinterpret_cast<const float4*>(&hl[(size_t)s * DD + h * 32]);
    float* op = &out[(size_t)d * DD + h * 32];
#pragma unroll
    for (int w = 0; w < 8; w++) {
        float4 hv = hs[w];
        redAdd4(op + w * 4, hv.x * alpha, hv.y * alpha, hv.z * alpha, hv.w * alpha);
    }
}

__global__ void bias_relu_kernel(float* __restrict__ out, const float* __restrict__ bias)
{
    int i = blockIdx.x * blockDim.x + threadIdx.x;
    if (i >= NN * DD) return;
    out[i] = fmaxf(out[i] + bias[i & 255], 0.0f);
}

// ---------------- attention: one query per lane, K/V broadcast from smem ----------
__global__ void __launch_bounds__(256) attn_kernel(const float* __restrict__ qkv,
                                                   float* __restrict__ out)
{
    const int bh = blockIdx.x;          // 0..63
    const int b = bh >> 3, h = bh & 7;
    const int warp = threadIdx.x >> 5, lane = threadIdx.x & 31;
    const int q = blockIdx.y * 256 + warp * 32 + lane;
    const float* base = qkv + (size_t)b * LL * 768;

    float qv[32];
    const float* qp = base + q * 768 + h * 32;
#pragma unroll
    for (int c = 0; c < 32; c++) qv[c] = qp[c] * 0.17677669529663687f; // 1/sqrt(32)

    __shared__ __align__(16) float Ks[128 * 32];
    __shared__ __align__(16) float Vs[128 * 32];

    float m = -1e30f, s = 0.f;
    float acc[32];
#pragma unroll
    for (int c = 0; c < 32; c++) acc[c] = 0.f;

    for (int t = 0; t < 8; t++) {
        __syncthreads();
#pragma unroll
        for (int i = 0; i < 4; i++) {
            int f4 = threadIdx.x + i * 256;   // 0..1023
            int row = f4 >> 3, c4 = (f4 & 7) << 2;
            const float* kp = base + (size_t)(t * 128 + row) * 768 + 256 + h * 32 + c4;
            *(float4*)&Ks[row * 32 + c4] = *(const float4*)kp;
            *(float4*)&Vs[row * 32 + c4] = *(const float4*)(kp + 256);
        }
        __syncthreads();
        for (int j = 0; j < 128; j++) {
            const float4* kr = reinterpret_cast<const float4*>(&Ks[j * 32]);
            float sc = 0.f;
#pragma unroll
            for (int w = 0; w < 8; w++) {
                float4 kk = kr[w];
                sc += qv[4 * w + 0] * kk.x + qv[4 * w + 1] * kk.y
                    + qv[4 * w + 2] * kk.z + qv[4 * w + 3] * kk.w;
            }
            const float4* vr = reinterpret_cast<const float4*>(&Vs[j * 32]);
            if (__any_sync(0xffffffffu, sc > m)) {
                // heavy path: per-lane rescale (corr==1 for lanes whose max stands)
                float mn = fmaxf(m, sc);
                float corr = __expf(m - mn);
                float p = __expf(sc - mn);
                s = s * corr + p;
                m = mn;
#pragma unroll
                for (int w = 0; w < 8; w++) {
                    float4 vv = vr[w];
                    acc[4 * w + 0] = acc[4 * w + 0] * corr + p * vv.x;
                    acc[4 * w + 1] = acc[4 * w + 1] * corr + p * vv.y;
                    acc[4 * w + 2] = acc[4 * w + 2] * corr + p * vv.z;
                    acc[4 * w + 3] = acc[4 * w + 3] * corr + p * vv.w;
                }
            } else {
                float p = __expf(sc - m);
                s += p;
#pragma unroll
                for (int w = 0; w < 8; w++) {
                    float4 vv = vr[w];
                    acc[4 * w + 0] += p * vv.x;
                    acc[4 * w + 1] += p * vv.y;
                    acc[4 * w + 2] += p * vv.z;
                    acc[4 * w + 3] += p * vv.w;
                }
            }
        }
    }

    float inv = 1.0f / s;
    float* op = out + (size_t)(b * LL + q) * DD + h * 32;
#pragma unroll
    for (int w = 0; w < 8; w++) {
        float4 o;
        o.x = acc[4 * w + 0] * inv;
        o.y = acc[4 * w + 1] * inv;
        o.z = acc[4 * w + 2] * inv;
        o.w = acc[4 * w + 3] * inv;
        *(float4*)(op + 4 * w) = o;
    }
}

// ---------------- residual + LayerNorm ----------------
__global__ void __launch_bounds__(256) ln_res_kernel(
    const float* __restrict__ x, const float* __restrict__ r,
    const float* __restrict__ w, const float* __restrict__ b,
    float* __restrict__ y)
{
    int row = blockIdx.x, t = threadIdx.x;
    size_t i = (size_t)row * DD + t;
    float v = x[i] + r[i];
    float s1 = v, s2 = v * v;
#pragma unroll
    for (int o = 16; o; o >>= 1) {
        s1 += __shfl_xor_sync(0xffffffffu, s1, o);
        s2 += __shfl_xor_sync(0xffffffffu, s2, o);
    }
    __shared__ float a1[8], a2[8];
    int wid = t >> 5, lane = t & 31;
    if (lane == 0) { a1[wid] = s1; a2[wid] = s2; }
    __syncthreads();
    float S1 = 0.f, S2 = 0.f;
#pragma unroll
    for (int k = 0; k < 8; k++) { S1 += a1[k]; S2 += a2[k]; }
    float mu = S1 * (1.0f / DD);
    float var = S2 * (1.0f / DD) - mu * mu;
    y[i] = (v - mu) * rsqrtf(var + 1e-5f) * w[t] + b[t];
}

// ---------------- final prediction ----------------
__global__ void __launch_bounds__(256) pred_kernel(
    const float* __restrict__ x, const float* __restrict__ pw,
    const float* __restrict__ pb, float* __restrict__ out)
{
    int n = blockIdx.x * 8 + (threadIdx.x >> 5);
    int lane = threadIdx.x & 31;
    const float* xr = x + (size_t)n * DD;
    float xv[8];
#pragma unroll
    for (int k = 0; k < 8; k++) xv[k] = xr[lane + 32 * k];
    float a0 = 0.f, a1 = 0.f, a2 = 0.f;
#pragma unroll
    for (int k = 0; k < 8; k++) {
        int c = lane + 32 * k;
        a0 += xv[k] * pw[0 * DD + c];
        a1 += xv[k] * pw[1 * DD + c];
        a2 += xv[k] * pw[2 * DD + c];
    }
#pragma unroll
    for (int o = 16; o; o >>= 1) {
        a0 += __shfl_xor_sync(0xffffffffu, a0, o);
        a1 += __shfl_xor_sync(0xffffffffu, a1, o);
        a2 += __shfl_xor_sync(0xffffffffu, a2, o);
    }
    if (lane == 0) {
        out[n * 3 + 0] = a0 + pb[0];
        out[n * 3 + 1] = a1 + pb[1];
        out[n * 3 + 2] = a2 + pb[2];
    }
}

// ---------------- host orchestration ----------------
extern "C" void kernel_launch(void* const* d_in, const int* in_sizes, int n_in,
                              void* d_out, int out_size)
{
    const float* x        = (const float*)d_in[0];
    const int*   ei       = (const int*)  d_in[1];
    const float* gat_W0   = (const float*)d_in[3];
    const float* gat_W12  = (const float*)d_in[4];
    const float* att_src  = (const float*)d_in[5];
    const float* att_dst  = (const float*)d_in[6];
    const float* gat_bias = (const float*)d_in[7];
    const float* qkv_w    = (const float*)d_in[8];
    const float* qkv_b    = (const float*)d_in[9];
    const float* out_w    = (const float*)d_in[10];
    const float* out_b    = (const float*)d_in[11];
    const float* ln1_w    = (const float*)d_in[12];
    const float* ln1_b    = (const float*)d_in[13];
    const float* ln2_w    = (const float*)d_in[14];
    const float* ln2_b    = (const float*)d_in[15];
    const float* ff1_w    = (const float*)d_in[16];
    const float* ff1_b    = (const float*)d_in[17];
    const float* ff2_w    = (const float*)d_in[18];
    const float* ff2_b    = (const float*)d_in[19];
    const float* pred_w   = (const float*)d_in[20];
    const float* pred_b   = (const float*)d_in[21];

    const int E = in_sizes[1] / 2;
    const int Etot = E + NN;
    const int* src = ei;
    const int* dst = ei + E;

    float *hl, *h0, *h1, *as_, *ad_, *m_, *ss_, *e_, *qkv, *attn, *tmp, *ff;
    cudaGetSymbolAddress((void**)&hl,   g_hl);
    cudaGetSymbolAddress((void**)&h0,   g_h0);
    cudaGetSymbolAddress((void**)&h1,   g_h1);
    cudaGetSymbolAddress((void**)&as_,  g_as);
    cudaGetSymbolAddress((void**)&ad_,  g_ad);
    cudaGetSymbolAddress((void**)&m_,   g_m);
    cudaGetSymbolAddress((void**)&ss_,  g_ss);
    cudaGetSymbolAddress((void**)&e_,   g_e);
    cudaGetSymbolAddress((void**)&qkv,  g_qkv);
    cudaGetSymbolAddress((void**)&attn, g_attn);
    cudaGetSymbolAddress((void**)&tmp,  g_tmp);
    cudaGetSymbolAddress((void**)&ff,   g_ff);

    const int eb = (Etot + 255) / 256;

    auto gat_layer = [&](const float* in, int Din, const float* W,
                         const float* atts, const float* attd, const float* bias,
                         float* outp) {
        tgemm_kernel<0><<<dim3(DD / 128, NN / 128), 256>>>(in, W, nullptr, hl, NN, DD, Din);
        gat_coef_kernel<<<(NN * HH) / 256, 256>>>(hl, atts, attd, as_, ad_);
        gat_init_kernel<<<(NN * DD) / 256, 256>>>(outp, m_, ss_);
        gat_edge_max_kernel<<<eb, 256>>>(src, dst, E, Etot, as_, ad_, e_, m_);
        gat_edge_exp_kernel<<<eb, 256>>>(dst, E, Etot, e_, m_, ss_);
        gat_agg_kernel<<<(Etot * 8 + 255) / 256, 256>>>(src, dst, E, Etot, e_, ss_, hl, outp);
        bias_relu_kernel<<<(NN * DD) / 256, 256>>>(outp, bias);
    };

    gat_layer(x,  INC, gat_W0,            att_src,           att_dst,           gat_bias,          h0);
    gat_layer(h0, DD,  gat_W12,           att_src + HH * CC, att_dst + HH * CC, gat_bias + DD,     h1);
    gat_layer(h1, DD,  gat_W12 + DD * DD, att_src + 2*HH*CC, att_dst + 2*HH*CC, gat_bias + 2 * DD, h0);

    for (int l = 0; l < 2; l++) {
        const float* qw  = qkv_w + (size_t)l * 3 * DD * DD;
        const float* qb  = qkv_b + l * 3 * DD;
        const float* ow  = out_w + (size_t)l * DD * DD;
        const float* ob  = out_b + l * DD;
        const float* l1w = ln1_w + l * DD, * l1b = ln1_b + l * DD;
        const float* l2w = ln2_w + l * DD, * l2b = ln2_b + l * DD;
        const float* f1w = ff1_w + (size_t)l * DFF * DD;
        const float* f1b = ff1_b + l * DFF;
        const float* f2w = ff2_w + (size_t)l * DD * DFF;
        const float* f2b = ff2_b + l * DD;

        tgemm_kernel<1><<<dim3(3 * DD / 128, NN / 128), 256>>>(h0, qw, qb, qkv, NN, 3 * DD, DD);
        attn_kernel<<<dim3(BB * HH, LL / 256), 256>>>(qkv, attn);
        tgemm_kernel<1><<<dim3(DD / 128, NN / 128), 256>>>(attn, ow, ob, tmp, NN, DD, DD);
        ln_res_kernel<<<NN, 256>>>(h0, tmp, l1w, l1b, h1);
        tgemm_kernel<2><<<dim3(DFF / 128, NN / 128), 256>>>(h1, f1w, f1b, ff, NN, DFF, DD);
        tgemm_kernel<1><<<dim3(DD / 128, NN / 128), 256>>>(ff, f2w, f2b, tmp, NN, DD, DFF);
        ln_res_kernel<<<NN, 256>>>(h1, tmp, l2w, l2b, h0);
    }

    pred_kernel<<<NN / 8, 256>>>(h0, pred_w, pred_b, (float*)d_out);
}

// round 3
// speedup vs baseline: 1.8627x; 1.1796x over previous
#include <cuda_runtime.h>
#include <math.h>

#define NN   8192
#define BB   8
#define LL   1024
#define INC  64
#define HH   8
#define CC   32
#define DD   256
#define DFF  2048
#define EMAX 262144
#define ETOTMAX (EMAX + NN)

// ---------------- scratch (device globals; no runtime allocation) ----------------
__device__ float g_hl  [NN * DD];
__device__ float g_h0  [NN * DD];
__device__ float g_h1  [NN * DD];
__device__ float g_as  [NN * HH];
__device__ float g_ad  [NN * HH];
__device__ float g_ss  [NN * HH];
__device__ float g_qkv [NN * 3 * DD];
__device__ float g_attn[NN * DD];
__device__ float g_tmp [NN * DD];
__device__ float g_ff  [NN * DFF];

// ---------------- helpers ----------------
__device__ __forceinline__ void redAdd4(float* p, float a, float b, float c, float d) {
    asm volatile("red.global.add.v4.f32 [%0], {%1,%2,%3,%4};"
                 :: "l"(p), "f"(a), "f"(b), "f"(c), "f"(d) : "memory");
}

__device__ __forceinline__ float f2tf_f(float f) {
    unsigned u;
    asm("cvt.rna.tf32.f32 %0, %1;" : "=r"(u) : "f"(f));
    return __uint_as_float(u);
}

__device__ __forceinline__ void mma8(float* d, const unsigned* a, const unsigned* b) {
    asm volatile(
        "mma.sync.aligned.m16n8k8.row.col.f32.tf32.tf32.f32 "
        "{%0,%1,%2,%3},{%4,%5,%6,%7},{%8,%9},{%0,%1,%2,%3};"
        : "+f"(d[0]), "+f"(d[1]), "+f"(d[2]), "+f"(d[3])
        : "r"(a[0]), "r"(a[1]), "r"(a[2]), "r"(a[3]), "r"(b[0]), "r"(b[1]));
}

// ---------------- tensor-core GEMM: C[M,Nn] = A[M,K] * W[Nn,K]^T (+bias)(+relu) ----
// Single-pass tf32; conversion done once at smem-store time.
// BM=128, BN=128, BK=32; 8 warps = 4(m) x 2(n); warp tile 32m x 64n.
template<int BIASMODE>
__global__ void __launch_bounds__(256) tgemm_kernel(
    const float* __restrict__ A, const float* __restrict__ W,
    const float* __restrict__ bias, float* __restrict__ C,
    int M, int Nn, int K)
{
    __shared__ __align__(16) float As[128][36];
    __shared__ __align__(16) float Bs[128][36];
    const int bm = blockIdx.y * 128;
    const int bn = blockIdx.x * 128;
    const int tid = threadIdx.x;
    const int warp = tid >> 5, lane = tid & 31;
    const int wm = warp & 3, wn = warp >> 2;
    const int lg = lane >> 2;       // group id 0..7
    const int lt = lane & 3;        // thread-in-group 0..3

    float acc[2][8][4];
#pragma unroll
    for (int mt = 0; mt < 2; mt++)
#pragma unroll
        for (int nt = 0; nt < 8; nt++)
#pragma unroll
            for (int r = 0; r < 4; r++) acc[mt][nt][r] = 0.0f;

    for (int k0 = 0; k0 < K; k0 += 32) {
#pragma unroll
        for (int i = 0; i < 4; i++) {
            int f4 = tid + i * 256;              // 0..1023
            int row = f4 >> 3, c4 = (f4 & 7) << 2;
            float4 av = *(const float4*)&A[(size_t)(bm + row) * K + k0 + c4];
            float4 bv = *(const float4*)&W[(size_t)(bn + row) * K + k0 + c4];
            av.x = f2tf_f(av.x); av.y = f2tf_f(av.y);
            av.z = f2tf_f(av.z); av.w = f2tf_f(av.w);
            bv.x = f2tf_f(bv.x); bv.y = f2tf_f(bv.y);
            bv.z = f2tf_f(bv.z); bv.w = f2tf_f(bv.w);
            *(float4*)&As[row][c4] = av;
            *(float4*)&Bs[row][c4] = bv;
        }
        __syncthreads();
#pragma unroll
        for (int kk = 0; kk < 32; kk += 8) {
            unsigned ah[2][4], bf[8][2];
            const int c = kk + lt;
#pragma unroll
            for (int mt = 0; mt < 2; mt++) {
                int r = wm * 32 + mt * 16 + lg;
                ah[mt][0] = __float_as_uint(As[r][c]);
                ah[mt][1] = __float_as_uint(As[r + 8][c]);
                ah[mt][2] = __float_as_uint(As[r][c + 4]);
                ah[mt][3] = __float_as_uint(As[r + 8][c + 4]);
            }
#pragma unroll
            for (int nt = 0; nt < 8; nt++) {
                int n = wn * 64 + nt * 8 + lg;
                bf[nt][0] = __float_as_uint(Bs[n][c]);
                bf[nt][1] = __float_as_uint(Bs[n][c + 4]);
            }
#pragma unroll
            for (int mt = 0; mt < 2; mt++)
#pragma unroll
                for (int nt = 0; nt < 8; nt++)
                    mma8(acc[mt][nt], ah[mt], bf[nt]);
        }
        __syncthreads();
    }

#pragma unroll
    for (int mt = 0; mt < 2; mt++) {
#pragma unroll
        for (int nt = 0; nt < 8; nt++) {
            int row = bm + wm * 32 + mt * 16 + lg;
            int col = bn + wn * 64 + nt * 8 + (lt << 1);
            float b0 = 0.f, b1 = 0.f;
            if (BIASMODE > 0) { b0 = bias[col]; b1 = bias[col + 1]; }
            float v0 = acc[mt][nt][0] + b0, v1 = acc[mt][nt][1] + b1;
            float v2 = acc[mt][nt][2] + b0, v3 = acc[mt][nt][3] + b1;
            if (BIASMODE == 2) {
                v0 = fmaxf(v0, 0.f); v1 = fmaxf(v1, 0.f);
                v2 = fmaxf(v2, 0.f); v3 = fmaxf(v3, 0.f);
            }
            *(float2*)&C[(size_t)row * Nn + col] = make_float2(v0, v1);
            *(float2*)&C[(size_t)(row + 8) * Nn + col] = make_float2(v2, v3);
        }
    }
}

// ---------------- GAT kernels ----------------
__global__ void gat_coef_kernel(const float* __restrict__ hl,
                                const float* __restrict__ atts,
                                const float* __restrict__ attd,
                                float* __restrict__ as_, float* __restrict__ ad_)
{
    int t = blockIdx.x * blockDim.x + threadIdx.x;
    if (t >= NN * HH) return;
    int n = t >> 3, h = t & 7;
    const float4* hp = reinterpret_cast<const float4*>(&hl[(size_t)n * DD + h * 32]);
    const float4* sp = reinterpret_cast<const float4*>(&atts[h * 32]);
    const float4* dp = reinterpret_cast<const float4*>(&attd[h * 32]);
    float ss = 0.f, dd = 0.f;
#pragma unroll
    for (int w = 0; w < 8; w++) {
        float4 hv = hp[w], sv = sp[w], dv = dp[w];
        ss += hv.x * sv.x + hv.y * sv.y + hv.z * sv.z + hv.w * sv.w;
        dd += hv.x * dv.x + hv.y * dv.y + hv.z * dv.z + hv.w * dv.w;
    }
    as_[t] = ss;
    ad_[t] = dd;
}

__global__ void gat_init_kernel(float* __restrict__ out, float* __restrict__ s)
{
    int i = blockIdx.x * blockDim.x + threadIdx.x;
    if (i < NN * DD) out[i] = 0.0f;
    if (i < NN * HH) s[i] = 0.0f;
}

// Single fused edge pass: e -> leakyrelu -> exp -> (sum, weighted aggregate),
// all unnormalized; normalization happens in the epilogue.
// (No max-shift: logits are O(1), exp is safe, normalization is identical math.)
__global__ void gat_edge_fused_kernel(const int* __restrict__ src, const int* __restrict__ dst,
                                      int E, int Etot,
                                      const float* __restrict__ as_, const float* __restrict__ ad_,
                                      const float* __restrict__ hl,
                                      float* __restrict__ ssum, float* __restrict__ out)
{
    int idx = blockIdx.x * blockDim.x + threadIdx.x;
    if (idx >= Etot * 8) return;
    int e = idx >> 3, h = idx & 7;
    int s, d;
    if (e < E) { s = src[e]; d = dst[e]; } else { s = d = e - E; }
    float a = as_[s * 8 + h] + ad_[d * 8 + h];
    a = (a > 0.f) ? a : 0.2f * a;
    float p = __expf(a);
    atomicAdd(&ssum[d * 8 + h], p);
    const float4* hs = reinterpret_cast<const float4*>(&hl[(size_t)s * DD + h * 32]);
    float* op = &out[(size_t)d * DD + h * 32];
#pragma unroll
    for (int w = 0; w < 8; w++) {
        float4 hv = hs[w];
        redAdd4(op + w * 4, p * hv.x, p * hv.y, p * hv.z, p * hv.w);
    }
}

__global__ void gat_norm_bias_relu_kernel(float* __restrict__ out,
                                          const float* __restrict__ ssum,
                                          const float* __restrict__ bias)
{
    int i = blockIdx.x * blockDim.x + threadIdx.x;
    if (i >= NN * DD) return;
    int n = i >> 8;
    int h = (i & 255) >> 5;
    float inv = 1.0f / ssum[n * 8 + h];
    out[i] = fmaxf(out[i] * inv + bias[i & 255], 0.0f);
}

// ---------------- attention: one query per lane, K/V broadcast from smem ----------
__global__ void __launch_bounds__(256) attn_kernel(const float* __restrict__ qkv,
                                                   float* __restrict__ out)
{
    const int bh = blockIdx.x;          // 0..63
    const int b = bh >> 3, h = bh & 7;
    const int warp = threadIdx.x >> 5, lane = threadIdx.x & 31;
    const int q = blockIdx.y * 256 + warp * 32 + lane;
    const float* base = qkv + (size_t)b * LL * 768;

    float qv[32];
    const float* qp = base + q * 768 + h * 32;
#pragma unroll
    for (int c = 0; c < 32; c++) qv[c] = qp[c] * 0.17677669529663687f; // 1/sqrt(32)

    __shared__ __align__(16) float Ks[128 * 32];
    __shared__ __align__(16) float Vs[128 * 32];

    float m = -1e30f, s = 0.f;
    float acc[32];
#pragma unroll
    for (int c = 0; c < 32; c++) acc[c] = 0.f;

    for (int t = 0; t < 8; t++) {
        __syncthreads();
#pragma unroll
        for (int i = 0; i < 4; i++) {
            int f4 = threadIdx.x + i * 256;   // 0..1023
            int row = f4 >> 3, c4 = (f4 & 7) << 2;
            const float* kp = base + (size_t)(t * 128 + row) * 768 + 256 + h * 32 + c4;
            *(float4*)&Ks[row * 32 + c4] = *(const float4*)kp;
            *(float4*)&Vs[row * 32 + c4] = *(const float4*)(kp + 256);
        }
        __syncthreads();
        for (int j = 0; j < 128; j++) {
            const float4* kr = reinterpret_cast<const float4*>(&Ks[j * 32]);
            float sc = 0.f;
#pragma unroll
            for (int w = 0; w < 8; w++) {
                float4 kk = kr[w];
                sc += qv[4 * w + 0] * kk.x + qv[4 * w + 1] * kk.y
                    + qv[4 * w + 2] * kk.z + qv[4 * w + 3] * kk.w;
            }
            const float4* vr = reinterpret_cast<const float4*>(&Vs[j * 32]);
            if (__any_sync(0xffffffffu, sc > m)) {
                float mn = fmaxf(m, sc);
                float corr = __expf(m - mn);
                float p = __expf(sc - mn);
                s = s * corr + p;
                m = mn;
#pragma unroll
                for (int w = 0; w < 8; w++) {
                    float4 vv = vr[w];
                    acc[4 * w + 0] = acc[4 * w + 0] * corr + p * vv.x;
                    acc[4 * w + 1] = acc[4 * w + 1] * corr + p * vv.y;
                    acc[4 * w + 2] = acc[4 * w + 2] * corr + p * vv.z;
                    acc[4 * w + 3] = acc[4 * w + 3] * corr + p * vv.w;
                }
            } else {
                float p = __expf(sc - m);
                s += p;
#pragma unroll
                for (int w = 0; w < 8; w++) {
                    float4 vv = vr[w];
                    acc[4 * w + 0] += p * vv.x;
                    acc[4 * w + 1] += p * vv.y;
                    acc[4 * w + 2] += p * vv.z;
                    acc[4 * w + 3] += p * vv.w;
                }
            }
        }
    }

    float inv = 1.0f / s;
    float* op = out + (size_t)(b * LL + q) * DD + h * 32;
#pragma unroll
    for (int w = 0; w < 8; w++) {
        float4 o;
        o.x = acc[4 * w + 0] * inv;
        o.y = acc[4 * w + 1] * inv;
        o.z = acc[4 * w + 2] * inv;
        o.w = acc[4 * w + 3] * inv;
        *(float4*)(op + 4 * w) = o;
    }
}

// ---------------- residual + LayerNorm ----------------
__global__ void __launch_bounds__(256) ln_res_kernel(
    const float* __restrict__ x, const float* __restrict__ r,
    const float* __restrict__ w, const float* __restrict__ b,
    float* __restrict__ y)
{
    int row = blockIdx.x, t = threadIdx.x;
    size_t i = (size_t)row * DD + t;
    float v = x[i] + r[i];
    float s1 = v, s2 = v * v;
#pragma unroll
    for (int o = 16; o; o >>= 1) {
        s1 += __shfl_xor_sync(0xffffffffu, s1, o);
        s2 += __shfl_xor_sync(0xffffffffu, s2, o);
    }
    __shared__ float a1[8], a2[8];
    int wid = t >> 5, lane = t & 31;
    if (lane == 0) { a1[wid] = s1; a2[wid] = s2; }
    __syncthreads();
    float S1 = 0.f, S2 = 0.f;
#pragma unroll
    for (int k = 0; k < 8; k++) { S1 += a1[k]; S2 += a2[k]; }
    float mu = S1 * (1.0f / DD);
    float var = S2 * (1.0f / DD) - mu * mu;
    y[i] = (v - mu) * rsqrtf(var + 1e-5f) * w[t] + b[t];
}

// ---------------- final prediction ----------------
__global__ void __launch_bounds__(256) pred_kernel(
    const float* __restrict__ x, const float* __restrict__ pw,
    const float* __restrict__ pb, float* __restrict__ out)
{
    int n = blockIdx.x * 8 + (threadIdx.x >> 5);
    int lane = threadIdx.x & 31;
    const float* xr = x + (size_t)n * DD;
    float xv[8];
#pragma unroll
    for (int k = 0; k < 8; k++) xv[k] = xr[lane + 32 * k];
    float a0 = 0.f, a1 = 0.f, a2 = 0.f;
#pragma unroll
    for (int k = 0; k < 8; k++) {
        int c = lane + 32 * k;
        a0 += xv[k] * pw[0 * DD + c];
        a1 += xv[k] * pw[1 * DD + c];
        a2 += xv[k] * pw[2 * DD + c];
    }
#pragma unroll
    for (int o = 16; o; o >>= 1) {
        a0 += __shfl_xor_sync(0xffffffffu, a0, o);
        a1 += __shfl_xor_sync(0xffffffffu, a1, o);
        a2 += __shfl_xor_sync(0xffffffffu, a2, o);
    }
    if (lane == 0) {
        out[n * 3 + 0] = a0 + pb[0];
        out[n * 3 + 1] = a1 + pb[1];
        out[n * 3 + 2] = a2 + pb[2];
    }
}

// ---------------- host orchestration ----------------
extern "C" void kernel_launch(void* const* d_in, const int* in_sizes, int n_in,
                              void* d_out, int out_size)
{
    const float* x        = (const float*)d_in[0];
    const int*   ei       = (const int*)  d_in[1];
    const float* gat_W0   = (const float*)d_in[3];
    const float* gat_W12  = (const float*)d_in[4];
    const float* att_src  = (const float*)d_in[5];
    const float* att_dst  = (const float*)d_in[6];
    const float* gat_bias = (const float*)d_in[7];
    const float* qkv_w    = (const float*)d_in[8];
    const float* qkv_b    = (const float*)d_in[9];
    const float* out_w    = (const float*)d_in[10];
    const float* out_b    = (const float*)d_in[11];
    const float* ln1_w    = (const float*)d_in[12];
    const float* ln1_b    = (const float*)d_in[13];
    const float* ln2_w    = (const float*)d_in[14];
    const float* ln2_b    = (const float*)d_in[15];
    const float* ff1_w    = (const float*)d_in[16];
    const float* ff1_b    = (const float*)d_in[17];
    const float* ff2_w    = (const float*)d_in[18];
    const float* ff2_b    = (const float*)d_in[19];
    const float* pred_w   = (const float*)d_in[20];
    const float* pred_b   = (const float*)d_in[21];

    const int E = in_sizes[1] / 2;
    const int Etot = E + NN;
    const int* src = ei;
    const int* dst = ei + E;

    float *hl, *h0, *h1, *as_, *ad_, *ss_, *qkv, *attn, *tmp, *ff;
    cudaGetSymbolAddress((void**)&hl,   g_hl);
    cudaGetSymbolAddress((void**)&h0,   g_h0);
    cudaGetSymbolAddress((void**)&h1,   g_h1);
    cudaGetSymbolAddress((void**)&as_,  g_as);
    cudaGetSymbolAddress((void**)&ad_,  g_ad);
    cudaGetSymbolAddress((void**)&ss_,  g_ss);
    cudaGetSymbolAddress((void**)&qkv,  g_qkv);
    cudaGetSymbolAddress((void**)&attn, g_attn);
    cudaGetSymbolAddress((void**)&tmp,  g_tmp);
    cudaGetSymbolAddress((void**)&ff,   g_ff);

    auto gat_layer = [&](const float* in, int Din, const float* W,
                         const float* atts, const float* attd, const float* bias,
                         float* outp) {
        tgemm_kernel<0><<<dim3(DD / 128, NN / 128), 256>>>(in, W, nullptr, hl, NN, DD, Din);
        gat_coef_kernel<<<(NN * HH) / 256, 256>>>(hl, atts, attd, as_, ad_);
        gat_init_kernel<<<(NN * DD) / 256, 256>>>(outp, ss_);
        gat_edge_fused_kernel<<<(Etot * 8 + 255) / 256, 256>>>(src, dst, E, Etot, as_, ad_, hl, ss_, outp);
        gat_norm_bias_relu_kernel<<<(NN * DD) / 256, 256>>>(outp, ss_, bias);
    };

    gat_layer(x,  INC, gat_W0,            att_src,           att_dst,           gat_bias,          h0);
    gat_layer(h0, DD,  gat_W12,           att_src + HH * CC, att_dst + HH * CC, gat_bias + DD,     h1);
    gat_layer(h1, DD,  gat_W12 + DD * DD, att_src + 2*HH*CC, att_dst + 2*HH*CC, gat_bias + 2 * DD, h0);

    for (int l = 0; l < 2; l++) {
        const float* qw  = qkv_w + (size_t)l * 3 * DD * DD;
        const float* qb  = qkv_b + l * 3 * DD;
        const float* ow  = out_w + (size_t)l * DD * DD;
        const float* ob  = out_b + l * DD;
        const float* l1w = ln1_w + l * DD, * l1b = ln1_b + l * DD;
        const float* l2w = ln2_w + l * DD, * l2b = ln2_b + l * DD;
        const float* f1w = ff1_w + (size_t)l * DFF * DD;
        const float* f1b = ff1_b + l * DFF;
        const float* f2w = ff2_w + (size_t)l * DD * DFF;
        const float* f2b = ff2_b + l * DD;

        tgemm_kernel<1><<<dim3(3 * DD / 128, NN / 128), 256>>>(h0, qw, qb, qkv, NN, 3 * DD, DD);
        attn_kernel<<<dim3(BB * HH, LL / 256), 256>>>(qkv, attn);
        tgemm_kernel<1><<<dim3(DD / 128, NN / 128), 256>>>(attn, ow, ob, tmp, NN, DD, DD);
        ln_res_kernel<<<NN, 256>>>(h0, tmp, l1w, l1b, h1);
        tgemm_kernel<2><<<dim3(DFF / 128, NN / 128), 256>>>(h1, f1w, f1b, ff, NN, DFF, DD);
        tgemm_kernel<1><<<dim3(DD / 128, NN / 128), 256>>>(ff, f2w, f2b, tmp, NN, DD, DFF);
        ln_res_kernel<<<NN, 256>>>(h1, tmp, l2w, l2b, h0);
    }

    pred_kernel<<<NN / 8, 256>>>(h0, pred_w, pred_b, (float*)d_out);
}

// round 4
// speedup vs baseline: 2.1901x; 1.1758x over previous
#include <cuda_runtime.h>
#include <math.h>

#define NN   8192
#define BB   8
#define LL   1024
#define INC  64
#define HH   8
#define CC   32
#define DD   256
#define DFF  2048
#define EMAX 262144
#define ETOTMAX (EMAX + NN)

// ---------------- scratch (device globals; no runtime allocation) ----------------
__device__ float g_hl  [NN * DD];
__device__ float g_h0  [NN * DD];
__device__ float g_h1  [NN * DD];
__device__ float g_as  [NN * HH];
__device__ float g_ad  [NN * HH];
__device__ float g_pe  [ETOTMAX * HH];   // per-(sorted-edge, head) exp weights
__device__ float g_qkv [NN * 3 * DD];
__device__ float g_attn[NN * DD];
__device__ float g_tmp [NN * DD];
__device__ float g_ff  [NN * DFF];
// CSR (built once per launch)
__device__ int   g_deg [NN];
__device__ int   g_off [NN + 1];
__device__ int   g_pos [NN];
__device__ int   g_esrc[ETOTMAX];
__device__ int   g_edst[ETOTMAX];

// ---------------- helpers ----------------
__device__ __forceinline__ float f2tf_f(float f) {
    unsigned u;
    asm("cvt.rna.tf32.f32 %0, %1;" : "=r"(u) : "f"(f));
    return __uint_as_float(u);
}

__device__ __forceinline__ void mma8(float* d, const unsigned* a, const unsigned* b) {
    asm volatile(
        "mma.sync.aligned.m16n8k8.row.col.f32.tf32.tf32.f32 "
        "{%0,%1,%2,%3},{%4,%5,%6,%7},{%8,%9},{%0,%1,%2,%3};"
        : "+f"(d[0]), "+f"(d[1]), "+f"(d[2]), "+f"(d[3])
        : "r"(a[0]), "r"(a[1]), "r"(a[2]), "r"(a[3]), "r"(b[0]), "r"(b[1]));
}

// ---------------- tensor-core GEMM: C[M,Nn] = A[M,K] * W[Nn,K]^T (+bias)(+relu) ----
template<int BIASMODE>
__global__ void __launch_bounds__(256) tgemm_kernel(
    const float* __restrict__ A, const float* __restrict__ W,
    const float* __restrict__ bias, float* __restrict__ C,
    int M, int Nn, int K)
{
    __shared__ __align__(16) float As[128][36];
    __shared__ __align__(16) float Bs[128][36];
    const int bm = blockIdx.y * 128;
    const int bn = blockIdx.x * 128;
    const int tid = threadIdx.x;
    const int warp = tid >> 5, lane = tid & 31;
    const int wm = warp & 3, wn = warp >> 2;
    const int lg = lane >> 2;
    const int lt = lane & 3;

    float acc[2][8][4];
#pragma unroll
    for (int mt = 0; mt < 2; mt++)
#pragma unroll
        for (int nt = 0; nt < 8; nt++)
#pragma unroll
            for (int r = 0; r < 4; r++) acc[mt][nt][r] = 0.0f;

    for (int k0 = 0; k0 < K; k0 += 32) {
#pragma unroll
        for (int i = 0; i < 4; i++) {
            int f4 = tid + i * 256;
            int row = f4 >> 3, c4 = (f4 & 7) << 2;
            float4 av = *(const float4*)&A[(size_t)(bm + row) * K + k0 + c4];
            float4 bv = *(const float4*)&W[(size_t)(bn + row) * K + k0 + c4];
            av.x = f2tf_f(av.x); av.y = f2tf_f(av.y);
            av.z = f2tf_f(av.z); av.w = f2tf_f(av.w);
            bv.x = f2tf_f(bv.x); bv.y = f2tf_f(bv.y);
            bv.z = f2tf_f(bv.z); bv.w = f2tf_f(bv.w);
            *(float4*)&As[row][c4] = av;
            *(float4*)&Bs[row][c4] = bv;
        }
        __syncthreads();
#pragma unroll
        for (int kk = 0; kk < 32; kk += 8) {
            unsigned ah[2][4], bf[8][2];
            const int c = kk + lt;
#pragma unroll
            for (int mt = 0; mt < 2; mt++) {
                int r = wm * 32 + mt * 16 + lg;
                ah[mt][0] = __float_as_uint(As[r][c]);
                ah[mt][1] = __float_as_uint(As[r + 8][c]);
                ah[mt][2] = __float_as_uint(As[r][c + 4]);
                ah[mt][3] = __float_as_uint(As[r + 8][c + 4]);
            }
#pragma unroll
            for (int nt = 0; nt < 8; nt++) {
                int n = wn * 64 + nt * 8 + lg;
                bf[nt][0] = __float_as_uint(Bs[n][c]);
                bf[nt][1] = __float_as_uint(Bs[n][c + 4]);
            }
#pragma unroll
            for (int mt = 0; mt < 2; mt++)
#pragma unroll
                for (int nt = 0; nt < 8; nt++)
                    mma8(acc[mt][nt], ah[mt], bf[nt]);
        }
        __syncthreads();
    }

#pragma unroll
    for (int mt = 0; mt < 2; mt++) {
#pragma unroll
        for (int nt = 0; nt < 8; nt++) {
            int row = bm + wm * 32 + mt * 16 + lg;
            int col = bn + wn * 64 + nt * 8 + (lt << 1);
            float b0 = 0.f, b1 = 0.f;
            if (BIASMODE > 0) { b0 = bias[col]; b1 = bias[col + 1]; }
            float v0 = acc[mt][nt][0] + b0, v1 = acc[mt][nt][1] + b1;
            float v2 = acc[mt][nt][2] + b0, v3 = acc[mt][nt][3] + b1;
            if (BIASMODE == 2) {
                v0 = fmaxf(v0, 0.f); v1 = fmaxf(v1, 0.f);
                v2 = fmaxf(v2, 0.f); v3 = fmaxf(v3, 0.f);
            }
            *(float2*)&C[(size_t)row * Nn + col] = make_float2(v0, v1);
            *(float2*)&C[(size_t)(row + 8) * Nn + col] = make_float2(v2, v3);
        }
    }
}

// ---------------- CSR build (once per launch) ----------------
__global__ void csr_zero_kernel() {
    int i = blockIdx.x * blockDim.x + threadIdx.x;
    if (i < NN) g_deg[i] = 0;
}

__global__ void csr_hist_kernel(const int* __restrict__ dst, int E, int Etot) {
    int e = blockIdx.x * blockDim.x + threadIdx.x;
    if (e >= Etot) return;
    int d = (e < E) ? dst[e] : (e - E);
    atomicAdd(&g_deg[d], 1);
}

// single block, 1024 threads, scans NN=8192 counts
__global__ void __launch_bounds__(1024) csr_scan_kernel() {
    __shared__ int ts[1024];
    int t = threadIdx.x;
    int base = t * 8;
    int local[8];
    int s = 0;
#pragma unroll
    for (int j = 0; j < 8; j++) { local[j] = s; s += g_deg[base + j]; }
    ts[t] = s;
    __syncthreads();
    for (int off = 1; off < 1024; off <<= 1) {
        int v = (t >= off) ? ts[t - off] : 0;
        __syncthreads();
        ts[t] += v;
        __syncthreads();
    }
    int prefix = (t == 0) ? 0 : ts[t - 1];
#pragma unroll
    for (int j = 0; j < 8; j++) {
        int o = prefix + local[j];
        g_off[base + j] = o;
        g_pos[base + j] = o;
    }
    if (t == 1023) g_off[NN] = ts[1023];
}

__global__ void csr_fill_kernel(const int* __restrict__ src, const int* __restrict__ dst,
                                int E, int Etot) {
    int e = blockIdx.x * blockDim.x + threadIdx.x;
    if (e >= Etot) return;
    int s, d;
    if (e < E) { s = src[e]; d = dst[e]; } else { s = d = e - E; }
    int p = atomicAdd(&g_pos[d], 1);
    g_esrc[p] = s;
    g_edst[p] = d;
}

// ---------------- GAT kernels ----------------
__global__ void gat_coef_kernel(const float* __restrict__ hl,
                                const float* __restrict__ atts,
                                const float* __restrict__ attd,
                                float* __restrict__ as_, float* __restrict__ ad_)
{
    int t = blockIdx.x * blockDim.x + threadIdx.x;
    if (t >= NN * HH) return;
    int n = t >> 3, h = t & 7;
    const float4* hp = reinterpret_cast<const float4*>(&hl[(size_t)n * DD + h * 32]);
    const float4* sp = reinterpret_cast<const float4*>(&atts[h * 32]);
    const float4* dp = reinterpret_cast<const float4*>(&attd[h * 32]);
    float ss = 0.f, dd = 0.f;
#pragma unroll
    for (int w = 0; w < 8; w++) {
        float4 hv = hp[w], sv = sp[w], dv = dp[w];
        ss += hv.x * sv.x + hv.y * sv.y + hv.z * sv.z + hv.w * sv.w;
        dd += hv.x * dv.x + hv.y * dv.y + hv.z * dv.z + hv.w * dv.w;
    }
    as_[t] = ss;
    ad_[t] = dd;
}

// per sorted edge: compute 8 head exp-weights, write coalesced
__global__ void gat_edge_p_kernel(int Etot,
                                  const float* __restrict__ as_,
                                  const float* __restrict__ ad_,
                                  float* __restrict__ pe)
{
    int i = blockIdx.x * blockDim.x + threadIdx.x;
    if (i >= Etot) return;
    int s = g_esrc[i], d = g_edst[i];
    float4 s0 = *(const float4*)&as_[s * 8];
    float4 s1 = *(const float4*)&as_[s * 8 + 4];
    float4 d0 = *(const float4*)&ad_[d * 8];
    float4 d1 = *(const float4*)&ad_[d * 8 + 4];
    float a[8] = {s0.x + d0.x, s0.y + d0.y, s0.z + d0.z, s0.w + d0.w,
                  s1.x + d1.x, s1.y + d1.y, s1.z + d1.z, s1.w + d1.w};
#pragma unroll
    for (int h = 0; h < 8; h++) {
        float t = a[h];
        t = (t > 0.f) ? t : 0.2f * t;
        a[h] = __expf(t);
    }
    *(float4*)&pe[(size_t)i * 8]     = make_float4(a[0], a[1], a[2], a[3]);
    *(float4*)&pe[(size_t)i * 8 + 4] = make_float4(a[4], a[5], a[6], a[7]);
}

// gather: block per dst node, warp per head, lane per channel; fused norm+bias+relu
__global__ void __launch_bounds__(256) gat_gather_kernel(
    const float* __restrict__ hl, const float* __restrict__ pe,
    const float* __restrict__ bias, float* __restrict__ out)
{
    const int d = blockIdx.x;
    const int h = threadIdx.x >> 5, lane = threadIdx.x & 31;
    const int beg = g_off[d], end = g_off[d + 1];
    const int hc = h * 32 + lane;

    float acc0 = 0.f, acc1 = 0.f, acc2 = 0.f, acc3 = 0.f;
    float ss = 0.f;
    int i = beg;
    for (; i + 4 <= end; i += 4) {
        int s0 = g_esrc[i], s1 = g_esrc[i + 1], s2 = g_esrc[i + 2], s3 = g_esrc[i + 3];
        float p0 = pe[(size_t)i * 8 + h];
        float p1 = pe[(size_t)(i + 1) * 8 + h];
        float p2 = pe[(size_t)(i + 2) * 8 + h];
        float p3 = pe[(size_t)(i + 3) * 8 + h];
        float v0 = hl[(size_t)s0 * DD + hc];
        float v1 = hl[(size_t)s1 * DD + hc];
        float v2 = hl[(size_t)s2 * DD + hc];
        float v3 = hl[(size_t)s3 * DD + hc];
        ss += (p0 + p1) + (p2 + p3);
        acc0 = fmaf(p0, v0, acc0);
        acc1 = fmaf(p1, v1, acc1);
        acc2 = fmaf(p2, v2, acc2);
        acc3 = fmaf(p3, v3, acc3);
    }
    for (; i < end; i++) {
        int s0 = g_esrc[i];
        float p0 = pe[(size_t)i * 8 + h];
        ss += p0;
        acc0 = fmaf(p0, hl[(size_t)s0 * DD + hc], acc0);
    }
    float acc = (acc0 + acc1) + (acc2 + acc3);
    out[(size_t)d * DD + hc] = fmaxf(acc / ss + bias[hc], 0.f);
}

// ---------------- attention: one query per lane, K/V broadcast from smem ----------
__global__ void __launch_bounds__(256) attn_kernel(const float* __restrict__ qkv,
                                                   float* __restrict__ out)
{
    const int bh = blockIdx.x;
    const int b = bh >> 3, h = bh & 7;
    const int warp = threadIdx.x >> 5, lane = threadIdx.x & 31;
    const int q = blockIdx.y * 256 + warp * 32 + lane;
    const float* base = qkv + (size_t)b * LL * 768;

    float qv[32];
    const float* qp = base + q * 768 + h * 32;
#pragma unroll
    for (int c = 0; c < 32; c++) qv[c] = qp[c] * 0.17677669529663687f;

    __shared__ __align__(16) float Ks[128 * 32];
    __shared__ __align__(16) float Vs[128 * 32];

    float m = -1e30f, s = 0.f;
    float acc[32];
#pragma unroll
    for (int c = 0; c < 32; c++) acc[c] = 0.f;

    for (int t = 0; t < 8; t++) {
        __syncthreads();
#pragma unroll
        for (int i = 0; i < 4; i++) {
            int f4 = threadIdx.x + i * 256;
            int row = f4 >> 3, c4 = (f4 & 7) << 2;
            const float* kp = base + (size_t)(t * 128 + row) * 768 + 256 + h * 32 + c4;
            *(float4*)&Ks[row * 32 + c4] = *(const float4*)kp;
            *(float4*)&Vs[row * 32 + c4] = *(const float4*)(kp + 256);
        }
        __syncthreads();
        for (int j = 0; j < 128; j++) {
            const float4* kr = reinterpret_cast<const float4*>(&Ks[j * 32]);
            float sc = 0.f;
#pragma unroll
            for (int w = 0; w < 8; w++) {
                float4 kk = kr[w];
                sc += qv[4 * w + 0] * kk.x + qv[4 * w + 1] * kk.y
                    + qv[4 * w + 2] * kk.z + qv[4 * w + 3] * kk.w;
            }
            const float4* vr = reinterpret_cast<const float4*>(&Vs[j * 32]);
            if (__any_sync(0xffffffffu, sc > m)) {
                float mn = fmaxf(m, sc);
                float corr = __expf(m - mn);
                float p = __expf(sc - mn);
                s = s * corr + p;
                m = mn;
#pragma unroll
                for (int w = 0; w < 8; w++) {
                    float4 vv = vr[w];
                    acc[4 * w + 0] = acc[4 * w + 0] * corr + p * vv.x;
                    acc[4 * w + 1] = acc[4 * w + 1] * corr + p * vv.y;
                    acc[4 * w + 2] = acc[4 * w + 2] * corr + p * vv.z;
                    acc[4 * w + 3] = acc[4 * w + 3] * corr + p * vv.w;
                }
            } else {
                float p = __expf(sc - m);
                s += p;
#pragma unroll
                for (int w = 0; w < 8; w++) {
                    float4 vv = vr[w];
                    acc[4 * w + 0] += p * vv.x;
                    acc[4 * w + 1] += p * vv.y;
                    acc[4 * w + 2] += p * vv.z;
                    acc[4 * w + 3] += p * vv.w;
                }
            }
        }
    }

    float inv = 1.0f / s;
    float* op = out + (size_t)(b * LL + q) * DD + h * 32;
#pragma unroll
    for (int w = 0; w < 8; w++) {
        float4 o;
        o.x = acc[4 * w + 0] * inv;
        o.y = acc[4 * w + 1] * inv;
        o.z = acc[4 * w + 2] * inv;
        o.w = acc[4 * w + 3] * inv;
        *(float4*)(op + 4 * w) = o;
    }
}

// ---------------- residual + LayerNorm ----------------
__global__ void __launch_bounds__(256) ln_res_kernel(
    const float* __restrict__ x, const float* __restrict__ r,
    const float* __restrict__ w, const float* __restrict__ b,
    float* __restrict__ y)
{
    int row = blockIdx.x, t = threadIdx.x;
    size_t i = (size_t)row * DD + t;
    float v = x[i] + r[i];
    float s1 = v, s2 = v * v;
#pragma unroll
    for (int o = 16; o; o >>= 1) {
        s1 += __shfl_xor_sync(0xffffffffu, s1, o);
        s2 += __shfl_xor_sync(0xffffffffu, s2, o);
    }
    __shared__ float a1[8], a2[8];
    int wid = t >> 5, lane = t & 31;
    if (lane == 0) { a1[wid] = s1; a2[wid] = s2; }
    __syncthreads();
    float S1 = 0.f, S2 = 0.f;
#pragma unroll
    for (int k = 0; k < 8; k++) { S1 += a1[k]; S2 += a2[k]; }
    float mu = S1 * (1.0f / DD);
    float var = S2 * (1.0f / DD) - mu * mu;
    y[i] = (v - mu) * rsqrtf(var + 1e-5f) * w[t] + b[t];
}

// ---------------- final prediction ----------------
__global__ void __launch_bounds__(256) pred_kernel(
    const float* __restrict__ x, const float* __restrict__ pw,
    const float* __restrict__ pb, float* __restrict__ out)
{
    int n = blockIdx.x * 8 + (threadIdx.x >> 5);
    int lane = threadIdx.x & 31;
    const float* xr = x + (size_t)n * DD;
    float xv[8];
#pragma unroll
    for (int k = 0; k < 8; k++) xv[k] = xr[lane + 32 * k];
    float a0 = 0.f, a1 = 0.f, a2 = 0.f;
#pragma unroll
    for (int k = 0; k < 8; k++) {
        int c = lane + 32 * k;
        a0 += xv[k] * pw[0 * DD + c];
        a1 += xv[k] * pw[1 * DD + c];
        a2 += xv[k] * pw[2 * DD + c];
    }
#pragma unroll
    for (int o = 16; o; o >>= 1) {
        a0 += __shfl_xor_sync(0xffffffffu, a0, o);
        a1 += __shfl_xor_sync(0xffffffffu, a1, o);
        a2 += __shfl_xor_sync(0xffffffffu, a2, o);
    }
    if (lane == 0) {
        out[n * 3 + 0] = a0 + pb[0];
        out[n * 3 + 1] = a1 + pb[1];
        out[n * 3 + 2] = a2 + pb[2];
    }
}

// ---------------- host orchestration ----------------
extern "C" void kernel_launch(void* const* d_in, const int* in_sizes, int n_in,
                              void* d_out, int out_size)
{
    const float* x        = (const float*)d_in[0];
    const int*   ei       = (const int*)  d_in[1];
    const float* gat_W0   = (const float*)d_in[3];
    const float* gat_W12  = (const float*)d_in[4];
    const float* att_src  = (const float*)d_in[5];
    const float* att_dst  = (const float*)d_in[6];
    const float* gat_bias = (const float*)d_in[7];
    const float* qkv_w    = (const float*)d_in[8];
    const float* qkv_b    = (const float*)d_in[9];
    const float* out_w    = (const float*)d_in[10];
    const float* out_b    = (const float*)d_in[11];
    const float* ln1_w    = (const float*)d_in[12];
    const float* ln1_b    = (const float*)d_in[13];
    const float* ln2_w    = (const float*)d_in[14];
    const float* ln2_b    = (const float*)d_in[15];
    const float* ff1_w    = (const float*)d_in[16];
    const float* ff1_b    = (const float*)d_in[17];
    const float* ff2_w    = (const float*)d_in[18];
    const float* ff2_b    = (const float*)d_in[19];
    const float* pred_w   = (const float*)d_in[20];
    const float* pred_b   = (const float*)d_in[21];

    const int E = in_sizes[1] / 2;
    const int Etot = E + NN;
    const int* src = ei;
    const int* dst = ei + E;

    float *hl, *h0, *h1, *as_, *ad_, *pe, *qkv, *attn, *tmp, *ff;
    cudaGetSymbolAddress((void**)&hl,   g_hl);
    cudaGetSymbolAddress((void**)&h0,   g_h0);
    cudaGetSymbolAddress((void**)&h1,   g_h1);
    cudaGetSymbolAddress((void**)&as_,  g_as);
    cudaGetSymbolAddress((void**)&ad_,  g_ad);
    cudaGetSymbolAddress((void**)&pe,   g_pe);
    cudaGetSymbolAddress((void**)&qkv,  g_qkv);
    cudaGetSymbolAddress((void**)&attn, g_attn);
    cudaGetSymbolAddress((void**)&tmp,  g_tmp);
    cudaGetSymbolAddress((void**)&ff,   g_ff);

    const int eb = (Etot + 255) / 256;

    // CSR build (once)
    csr_zero_kernel<<<(NN + 255) / 256, 256>>>();
    csr_hist_kernel<<<eb, 256>>>(dst, E, Etot);
    csr_scan_kernel<<<1, 1024>>>();
    csr_fill_kernel<<<eb, 256>>>(src, dst, E, Etot);

    auto gat_layer = [&](const float* in, int Din, const float* W,
                         const float* atts, const float* attd, const float* bias,
                         float* outp) {
        tgemm_kernel<0><<<dim3(DD / 128, NN / 128), 256>>>(in, W, nullptr, hl, NN, DD, Din);
        gat_coef_kernel<<<(NN * HH) / 256, 256>>>(hl, atts, attd, as_, ad_);
        gat_edge_p_kernel<<<eb, 256>>>(Etot, as_, ad_, pe);
        gat_gather_kernel<<<NN, 256>>>(hl, pe, bias, outp);
    };

    gat_layer(x,  INC, gat_W0,            att_src,           att_dst,           gat_bias,          h0);
    gat_layer(h0, DD,  gat_W12,           att_src + HH * CC, att_dst + HH * CC, gat_bias + DD,     h1);
    gat_layer(h1, DD,  gat_W12 + DD * DD, att_src + 2*HH*CC, att_dst + 2*HH*CC, gat_bias + 2 * DD, h0);

    for (int l = 0; l < 2; l++) {
        const float* qw  = qkv_w + (size_t)l * 3 * DD * DD;
        const float* qb  = qkv_b + l * 3 * DD;
        const float* ow  = out_w + (size_t)l * DD * DD;
        const float* ob  = out_b + l * DD;
        const float* l1w = ln1_w + l * DD, * l1b = ln1_b + l * DD;
        const float* l2w = ln2_w + l * DD, * l2b = ln2_b + l * DD;
        const float* f1w = ff1_w + (size_t)l * DFF * DD;
        const float* f1b = ff1_b + l * DFF;
        const float* f2w = ff2_w + (size_t)l * DD * DFF;
        const float* f2b = ff2_b + l * DD;

        tgemm_kernel<1><<<dim3(3 * DD / 128, NN / 128), 256>>>(h0, qw, qb, qkv, NN, 3 * DD, DD);
        attn_kernel<<<dim3(BB * HH, LL / 256), 256>>>(qkv, attn);
        tgemm_kernel<1><<<dim3(DD / 128, NN / 128), 256>>>(attn, ow, ob, tmp, NN, DD, DD);
        ln_res_kernel<<<NN, 256>>>(h0, tmp, l1w, l1b, h1);
        tgemm_kernel<2><<<dim3(DFF / 128, NN / 128), 256>>>(h1, f1w, f1b, ff, NN, DFF, DD);
        tgemm_kernel<1><<<dim3(DD / 128, NN / 128), 256>>>(ff, f2w, f2b, tmp, NN, DD, DFF);
        ln_res_kernel<<<NN, 256>>>(h1, tmp, l2w, l2b, h0);
    }

    pred_kernel<<<NN / 8, 256>>>(h0, pred_w, pred_b, (float*)d_out);
}

// round 5
// speedup vs baseline: 3.5333x; 1.6133x over previous
#include <cuda_runtime.h>
#include <math.h>

#define NN   8192
#define BB   8
#define LL   1024
#define INC  64
#define HH   8
#define CC   32
#define DD   256
#define DFF  2048
#define EMAX 262144
#define ETOTMAX (EMAX + NN)

// ---------------- scratch (device globals; no runtime allocation) ----------------
__device__ float g_hl  [NN * DD];
__device__ float g_h0  [NN * DD];
__device__ float g_h1  [NN * DD];
__device__ float g_as  [NN * HH];
__device__ float g_ad  [NN * HH];
__device__ float g_pe  [ETOTMAX * HH];
__device__ float g_qkv [NN * 3 * DD];
__device__ float g_attn[NN * DD];
__device__ float g_tmp [NN * DD];
__device__ float g_ff  [NN * DFF];
// CSR (built once per launch)
__device__ int   g_deg [NN];
__device__ int   g_off [NN + 1];
__device__ int   g_pos [NN];
__device__ int   g_esrc[ETOTMAX];
__device__ int   g_edst[ETOTMAX];

// ---------------- helpers ----------------
__device__ __forceinline__ float f2tf_f(float f) {
    unsigned u;
    asm("cvt.rna.tf32.f32 %0, %1;" : "=r"(u) : "f"(f));
    return __uint_as_float(u);
}

__device__ __forceinline__ void mma8(float* d, const unsigned* a, const unsigned* b) {
    asm volatile(
        "mma.sync.aligned.m16n8k8.row.col.f32.tf32.tf32.f32 "
        "{%0,%1,%2,%3},{%4,%5,%6,%7},{%8,%9},{%0,%1,%2,%3};"
        : "+f"(d[0]), "+f"(d[1]), "+f"(d[2]), "+f"(d[3])
        : "r"(a[0]), "r"(a[1]), "r"(a[2]), "r"(a[3]), "r"(b[0]), "r"(b[1]));
}

// ---------------- tensor-core GEMM with gmem prefetch pipeline -------------------
// C[M,Nn] = A[M,K] * W[Nn,K]^T (+bias)(+relu); tf32 single-pass.
template<int BIASMODE>
__global__ void __launch_bounds__(256) tgemm_kernel(
    const float* __restrict__ A, const float* __restrict__ W,
    const float* __restrict__ bias, float* __restrict__ C,
    int M, int Nn, int K)
{
    __shared__ __align__(16) float As[128][36];
    __shared__ __align__(16) float Bs[128][36];
    const int bm = blockIdx.y * 128;
    const int bn = blockIdx.x * 128;
    const int tid = threadIdx.x;
    const int warp = tid >> 5, lane = tid & 31;
    const int wm = warp & 3, wn = warp >> 2;
    const int lg = lane >> 2;
    const int lt = lane & 3;

    // load-index mapping (fixed per thread)
    int lrow[4], lc4[4];
#pragma unroll
    for (int i = 0; i < 4; i++) {
        int f4 = tid + i * 256;
        lrow[i] = f4 >> 3;
        lc4[i] = (f4 & 7) << 2;
    }

    float acc[2][8][4];
#pragma unroll
    for (int mt = 0; mt < 2; mt++)
#pragma unroll
        for (int nt = 0; nt < 8; nt++)
#pragma unroll
            for (int r = 0; r < 4; r++) acc[mt][nt][r] = 0.0f;

    float4 pa[4], pb[4];
#pragma unroll
    for (int i = 0; i < 4; i++) {
        pa[i] = *(const float4*)&A[(size_t)(bm + lrow[i]) * K + lc4[i]];
        pb[i] = *(const float4*)&W[(size_t)(bn + lrow[i]) * K + lc4[i]];
    }

    for (int k0 = 0; k0 < K; k0 += 32) {
#pragma unroll
        for (int i = 0; i < 4; i++) {
            float4 av = pa[i], bv = pb[i];
            av.x = f2tf_f(av.x); av.y = f2tf_f(av.y);
            av.z = f2tf_f(av.z); av.w = f2tf_f(av.w);
            bv.x = f2tf_f(bv.x); bv.y = f2tf_f(bv.y);
            bv.z = f2tf_f(bv.z); bv.w = f2tf_f(bv.w);
            *(float4*)&As[lrow[i]][lc4[i]] = av;
            *(float4*)&Bs[lrow[i]][lc4[i]] = bv;
        }
        __syncthreads();
        if (k0 + 32 < K) {
#pragma unroll
            for (int i = 0; i < 4; i++) {
                pa[i] = *(const float4*)&A[(size_t)(bm + lrow[i]) * K + k0 + 32 + lc4[i]];
                pb[i] = *(const float4*)&W[(size_t)(bn + lrow[i]) * K + k0 + 32 + lc4[i]];
            }
        }
#pragma unroll
        for (int kk = 0; kk < 32; kk += 8) {
            unsigned ah[2][4], bf[8][2];
            const int c = kk + lt;
#pragma unroll
            for (int mt = 0; mt < 2; mt++) {
                int r = wm * 32 + mt * 16 + lg;
                ah[mt][0] = __float_as_uint(As[r][c]);
                ah[mt][1] = __float_as_uint(As[r + 8][c]);
                ah[mt][2] = __float_as_uint(As[r][c + 4]);
                ah[mt][3] = __float_as_uint(As[r + 8][c + 4]);
            }
#pragma unroll
            for (int nt = 0; nt < 8; nt++) {
                int n = wn * 64 + nt * 8 + lg;
                bf[nt][0] = __float_as_uint(Bs[n][c]);
                bf[nt][1] = __float_as_uint(Bs[n][c + 4]);
            }
#pragma unroll
            for (int mt = 0; mt < 2; mt++)
#pragma unroll
                for (int nt = 0; nt < 8; nt++)
                    mma8(acc[mt][nt], ah[mt], bf[nt]);
        }
        __syncthreads();
    }

#pragma unroll
    for (int mt = 0; mt < 2; mt++) {
#pragma unroll
        for (int nt = 0; nt < 8; nt++) {
            int row = bm + wm * 32 + mt * 16 + lg;
            int col = bn + wn * 64 + nt * 8 + (lt << 1);
            float b0 = 0.f, b1 = 0.f;
            if (BIASMODE > 0) { b0 = bias[col]; b1 = bias[col + 1]; }
            float v0 = acc[mt][nt][0] + b0, v1 = acc[mt][nt][1] + b1;
            float v2 = acc[mt][nt][2] + b0, v3 = acc[mt][nt][3] + b1;
            if (BIASMODE == 2) {
                v0 = fmaxf(v0, 0.f); v1 = fmaxf(v1, 0.f);
                v2 = fmaxf(v2, 0.f); v3 = fmaxf(v3, 0.f);
            }
            *(float2*)&C[(size_t)row * Nn + col] = make_float2(v0, v1);
            *(float2*)&C[(size_t)(row + 8) * Nn + col] = make_float2(v2, v3);
        }
    }
}

// ---------------- CSR build (once per launch) ----------------
__global__ void csr_zero_kernel() {
    int i = blockIdx.x * blockDim.x + threadIdx.x;
    if (i < NN) g_deg[i] = 0;
}

__global__ void csr_hist_kernel(const int* __restrict__ dst, int E, int Etot) {
    int e = blockIdx.x * blockDim.x + threadIdx.x;
    if (e >= Etot) return;
    int d = (e < E) ? dst[e] : (e - E);
    atomicAdd(&g_deg[d], 1);
}

__global__ void __launch_bounds__(1024) csr_scan_kernel() {
    __shared__ int ts[1024];
    int t = threadIdx.x;
    int base = t * 8;
    int local[8];
    int s = 0;
#pragma unroll
    for (int j = 0; j < 8; j++) { local[j] = s; s += g_deg[base + j]; }
    ts[t] = s;
    __syncthreads();
    for (int off = 1; off < 1024; off <<= 1) {
        int v = (t >= off) ? ts[t - off] : 0;
        __syncthreads();
        ts[t] += v;
        __syncthreads();
    }
    int prefix = (t == 0) ? 0 : ts[t - 1];
#pragma unroll
    for (int j = 0; j < 8; j++) {
        int o = prefix + local[j];
        g_off[base + j] = o;
        g_pos[base + j] = o;
    }
    if (t == 1023) g_off[NN] = ts[1023];
}

__global__ void csr_fill_kernel(const int* __restrict__ src, const int* __restrict__ dst,
                                int E, int Etot) {
    int e = blockIdx.x * blockDim.x + threadIdx.x;
    if (e >= Etot) return;
    int s, d;
    if (e < E) { s = src[e]; d = dst[e]; } else { s = d = e - E; }
    int p = atomicAdd(&g_pos[d], 1);
    g_esrc[p] = s;
    g_edst[p] = d;
}

// ---------------- GAT kernels ----------------
__global__ void gat_coef_kernel(const float* __restrict__ hl,
                                const float* __restrict__ atts,
                                const float* __restrict__ attd,
                                float* __restrict__ as_, float* __restrict__ ad_)
{
    int t = blockIdx.x * blockDim.x + threadIdx.x;
    if (t >= NN * HH) return;
    int n = t >> 3, h = t & 7;
    const float4* hp = reinterpret_cast<const float4*>(&hl[(size_t)n * DD + h * 32]);
    const float4* sp = reinterpret_cast<const float4*>(&atts[h * 32]);
    const float4* dp = reinterpret_cast<const float4*>(&attd[h * 32]);
    float ss = 0.f, dd = 0.f;
#pragma unroll
    for (int w = 0; w < 8; w++) {
        float4 hv = hp[w], sv = sp[w], dv = dp[w];
        ss += hv.x * sv.x + hv.y * sv.y + hv.z * sv.z + hv.w * sv.w;
        dd += hv.x * dv.x + hv.y * dv.y + hv.z * dv.z + hv.w * dv.w;
    }
    as_[t] = ss;
    ad_[t] = dd;
}

__global__ void gat_edge_p_kernel(int Etot,
                                  const float* __restrict__ as_,
                                  const float* __restrict__ ad_,
                                  float* __restrict__ pe)
{
    int i = blockIdx.x * blockDim.x + threadIdx.x;
    if (i >= Etot) return;
    int s = g_esrc[i], d = g_edst[i];
    float4 s0 = *(const float4*)&as_[s * 8];
    float4 s1 = *(const float4*)&as_[s * 8 + 4];
    float4 d0 = *(const float4*)&ad_[d * 8];
    float4 d1 = *(const float4*)&ad_[d * 8 + 4];
    float a[8] = {s0.x + d0.x, s0.y + d0.y, s0.z + d0.z, s0.w + d0.w,
                  s1.x + d1.x, s1.y + d1.y, s1.z + d1.z, s1.w + d1.w};
#pragma unroll
    for (int h = 0; h < 8; h++) {
        float t = a[h];
        t = (t > 0.f) ? t : 0.2f * t;
        a[h] = __expf(t);
    }
    *(float4*)&pe[(size_t)i * 8]     = make_float4(a[0], a[1], a[2], a[3]);
    *(float4*)&pe[(size_t)i * 8 + 4] = make_float4(a[4], a[5], a[6], a[7]);
}

__global__ void __launch_bounds__(256) gat_gather_kernel(
    const float* __restrict__ hl, const float* __restrict__ pe,
    const float* __restrict__ bias, float* __restrict__ out)
{
    const int d = blockIdx.x;
    const int h = threadIdx.x >> 5, lane = threadIdx.x & 31;
    const int beg = g_off[d], end = g_off[d + 1];
    const int hc = h * 32 + lane;

    float acc0 = 0.f, acc1 = 0.f, acc2 = 0.f, acc3 = 0.f;
    float ss = 0.f;
    int i = beg;
    for (; i + 4 <= end; i += 4) {
        int s0 = g_esrc[i], s1 = g_esrc[i + 1], s2 = g_esrc[i + 2], s3 = g_esrc[i + 3];
        float p0 = pe[(size_t)i * 8 + h];
        float p1 = pe[(size_t)(i + 1) * 8 + h];
        float p2 = pe[(size_t)(i + 2) * 8 + h];
        float p3 = pe[(size_t)(i + 3) * 8 + h];
        float v0 = hl[(size_t)s0 * DD + hc];
        float v1 = hl[(size_t)s1 * DD + hc];
        float v2 = hl[(size_t)s2 * DD + hc];
        float v3 = hl[(size_t)s3 * DD + hc];
        ss += (p0 + p1) + (p2 + p3);
        acc0 = fmaf(p0, v0, acc0);
        acc1 = fmaf(p1, v1, acc1);
        acc2 = fmaf(p2, v2, acc2);
        acc3 = fmaf(p3, v3, acc3);
    }
    for (; i < end; i++) {
        int s0 = g_esrc[i];
        float p0 = pe[(size_t)i * 8 + h];
        ss += p0;
        acc0 = fmaf(p0, hl[(size_t)s0 * DD + hc], acc0);
    }
    float acc = (acc0 + acc1) + (acc2 + acc3);
    out[(size_t)d * DD + hc] = fmaxf(acc / ss + bias[hc], 0.f);
}

// ---------------- MMA flash-attention ----------------
// Block: one (b,h), 64 queries; 4 warps x 16 q-rows each. Key tiles of 64.
__global__ void __launch_bounds__(128) attn_mma_kernel(const float* __restrict__ qkv,
                                                       float* __restrict__ out)
{
    __shared__ __align__(16) float Qs[64][36];
    __shared__ __align__(16) float Ks[64][36];
    __shared__ __align__(16) float Vt[32][68];   // transposed V: [dh][key]
    __shared__ __align__(16) float Ps[64][68];   // warp-private P rows

    const int bh = blockIdx.x, b = bh >> 3, h = bh & 7;
    const int qt = blockIdx.y;
    const int tid = threadIdx.x;
    const int warp = tid >> 5, lane = tid & 31;
    const int lg = lane >> 2, lt = lane & 3;
    const float* base = qkv + (size_t)b * LL * 768;
    const float scale = 0.17677669529663687f;   // 1/sqrt(32)

    // stage Q (scaled, tf32)
#pragma unroll
    for (int i = 0; i < 4; i++) {
        int idx = tid + i * 128;                // 0..511
        int row = idx >> 3, c4 = (idx & 7) << 2;
        float4 v = *(const float4*)(base + (size_t)(qt * 64 + row) * 768 + h * 32 + c4);
        Qs[row][c4 + 0] = f2tf_f(v.x * scale);
        Qs[row][c4 + 1] = f2tf_f(v.y * scale);
        Qs[row][c4 + 2] = f2tf_f(v.z * scale);
        Qs[row][c4 + 3] = f2tf_f(v.w * scale);
    }

    float m0 = -1e30f, m1 = -1e30f, l0 = 0.f, l1 = 0.f;
    float o[4][4];
#pragma unroll
    for (int nt = 0; nt < 4; nt++)
#pragma unroll
        for (int r = 0; r < 4; r++) o[nt][r] = 0.f;

    const int r0 = warp * 16 + lg;

    for (int kt = 0; kt < 16; kt++) {
        __syncthreads();
#pragma unroll
        for (int i = 0; i < 4; i++) {
            int idx = tid + i * 128;
            int row = idx >> 3, c4 = (idx & 7) << 2;
            const float* kp = base + (size_t)(kt * 64 + row) * 768 + 256 + h * 32 + c4;
            float4 kv = *(const float4*)kp;
            Ks[row][c4 + 0] = f2tf_f(kv.x);
            Ks[row][c4 + 1] = f2tf_f(kv.y);
            Ks[row][c4 + 2] = f2tf_f(kv.z);
            Ks[row][c4 + 3] = f2tf_f(kv.w);
            float4 vv = *(const float4*)(kp + 256);
            Vt[c4 + 0][row] = f2tf_f(vv.x);
            Vt[c4 + 1][row] = f2tf_f(vv.y);
            Vt[c4 + 2][row] = f2tf_f(vv.z);
            Vt[c4 + 3][row] = f2tf_f(vv.w);
        }
        __syncthreads();

        // S = Q * K^T  (warp: 16q x 64k)
        float s[8][4];
#pragma unroll
        for (int nt = 0; nt < 8; nt++)
#pragma unroll
            for (int r = 0; r < 4; r++) s[nt][r] = 0.f;
#pragma unroll
        for (int kk = 0; kk < 4; kk++) {
            const int c = kk * 8 + lt;
            unsigned a[4];
            a[0] = __float_as_uint(Qs[r0][c]);
            a[1] = __float_as_uint(Qs[r0 + 8][c]);
            a[2] = __float_as_uint(Qs[r0][c + 4]);
            a[3] = __float_as_uint(Qs[r0 + 8][c + 4]);
#pragma unroll
            for (int nt = 0; nt < 8; nt++) {
                unsigned bb[2];
                bb[0] = __float_as_uint(Ks[nt * 8 + lg][c]);
                bb[1] = __float_as_uint(Ks[nt * 8 + lg][c + 4]);
                mma8(s[nt], a, bb);
            }
        }

        // online softmax (rows r0 and r0+8)
        float mx0 = -1e30f, mx1 = -1e30f;
#pragma unroll
        for (int nt = 0; nt < 8; nt++) {
            mx0 = fmaxf(mx0, fmaxf(s[nt][0], s[nt][1]));
            mx1 = fmaxf(mx1, fmaxf(s[nt][2], s[nt][3]));
        }
        mx0 = fmaxf(mx0, __shfl_xor_sync(0xffffffffu, mx0, 1));
        mx0 = fmaxf(mx0, __shfl_xor_sync(0xffffffffu, mx0, 2));
        mx1 = fmaxf(mx1, __shfl_xor_sync(0xffffffffu, mx1, 1));
        mx1 = fmaxf(mx1, __shfl_xor_sync(0xffffffffu, mx1, 2));
        float nm0 = fmaxf(m0, mx0), nm1 = fmaxf(m1, mx1);
        float c0 = __expf(m0 - nm0), c1 = __expf(m1 - nm1);
        m0 = nm0; m1 = nm1;

        float ps0 = 0.f, ps1 = 0.f;
#pragma unroll
        for (int nt = 0; nt < 8; nt++) {
            float p0 = __expf(s[nt][0] - m0);
            float p1 = __expf(s[nt][1] - m0);
            float p2 = __expf(s[nt][2] - m1);
            float p3 = __expf(s[nt][3] - m1);
            ps0 += p0 + p1;
            ps1 += p2 + p3;
            int col = nt * 8 + (lt << 1);
            Ps[r0][col]     = f2tf_f(p0);
            Ps[r0][col + 1] = f2tf_f(p1);
            Ps[r0 + 8][col]     = f2tf_f(p2);
            Ps[r0 + 8][col + 1] = f2tf_f(p3);
        }
        ps0 += __shfl_xor_sync(0xffffffffu, ps0, 1);
        ps0 += __shfl_xor_sync(0xffffffffu, ps0, 2);
        ps1 += __shfl_xor_sync(0xffffffffu, ps1, 1);
        ps1 += __shfl_xor_sync(0xffffffffu, ps1, 2);
        l0 = l0 * c0 + ps0;
        l1 = l1 * c1 + ps1;
#pragma unroll
        for (int nt = 0; nt < 4; nt++) {
            o[nt][0] *= c0; o[nt][1] *= c0;
            o[nt][2] *= c1; o[nt][3] *= c1;
        }
        __syncwarp();

        // O += P * V   (warp: 16q x 32dh, K=64 keys)
#pragma unroll
        for (int kk = 0; kk < 8; kk++) {
            const int c = kk * 8 + lt;
            unsigned a[4];
            a[0] = __float_as_uint(Ps[r0][c]);
            a[1] = __float_as_uint(Ps[r0 + 8][c]);
            a[2] = __float_as_uint(Ps[r0][c + 4]);
            a[3] = __float_as_uint(Ps[r0 + 8][c + 4]);
#pragma unroll
            for (int nt = 0; nt < 4; nt++) {
                unsigned bb[2];
                bb[0] = __float_as_uint(Vt[nt * 8 + lg][c]);
                bb[1] = __float_as_uint(Vt[nt * 8 + lg][c + 4]);
                mma8(o[nt], a, bb);
            }
        }
    }

    float inv0 = 1.0f / l0, inv1 = 1.0f / l1;
    int q0 = qt * 64 + r0;
    float* op = out + (size_t)(b * LL + q0) * DD + h * 32;
#pragma unroll
    for (int nt = 0; nt < 4; nt++) {
        int col = nt * 8 + (lt << 1);
        *(float2*)(op + col) = make_float2(o[nt][0] * inv0, o[nt][1] * inv0);
        *(float2*)(op + 8 * DD + col) = make_float2(o[nt][2] * inv1, o[nt][3] * inv1);
    }
}

// ---------------- residual + LayerNorm ----------------
__global__ void __launch_bounds__(256) ln_res_kernel(
    const float* __restrict__ x, const float* __restrict__ r,
    const float* __restrict__ w, const float* __restrict__ b,
    float* __restrict__ y)
{
    int row = blockIdx.x, t = threadIdx.x;
    size_t i = (size_t)row * DD + t;
    float v = x[i] + r[i];
    float s1 = v, s2 = v * v;
#pragma unroll
    for (int o = 16; o; o >>= 1) {
        s1 += __shfl_xor_sync(0xffffffffu, s1, o);
        s2 += __shfl_xor_sync(0xffffffffu, s2, o);
    }
    __shared__ float a1[8], a2[8];
    int wid = t >> 5, lane = t & 31;
    if (lane == 0) { a1[wid] = s1; a2[wid] = s2; }
    __syncthreads();
    float S1 = 0.f, S2 = 0.f;
#pragma unroll
    for (int k = 0; k < 8; k++) { S1 += a1[k]; S2 += a2[k]; }
    float mu = S1 * (1.0f / DD);
    float var = S2 * (1.0f / DD) - mu * mu;
    y[i] = (v - mu) * rsqrtf(var + 1e-5f) * w[t] + b[t];
}

// ---------------- final prediction ----------------
__global__ void __launch_bounds__(256) pred_kernel(
    const float* __restrict__ x, const float* __restrict__ pw,
    const float* __restrict__ pb, float* __restrict__ out)
{
    int n = blockIdx.x * 8 + (threadIdx.x >> 5);
    int lane = threadIdx.x & 31;
    const float* xr = x + (size_t)n * DD;
    float xv[8];
#pragma unroll
    for (int k = 0; k < 8; k++) xv[k] = xr[lane + 32 * k];
    float a0 = 0.f, a1 = 0.f, a2 = 0.f;
#pragma unroll
    for (int k = 0; k < 8; k++) {
        int c = lane + 32 * k;
        a0 += xv[k] * pw[0 * DD + c];
        a1 += xv[k] * pw[1 * DD + c];
        a2 += xv[k] * pw[2 * DD + c];
    }
#pragma unroll
    for (int o = 16; o; o >>= 1) {
        a0 += __shfl_xor_sync(0xffffffffu, a0, o);
        a1 += __shfl_xor_sync(0xffffffffu, a1, o);
        a2 += __shfl_xor_sync(0xffffffffu, a2, o);
    }
    if (lane == 0) {
        out[n * 3 + 0] = a0 + pb[0];
        out[n * 3 + 1] = a1 + pb[1];
        out[n * 3 + 2] = a2 + pb[2];
    }
}

// ---------------- host orchestration ----------------
extern "C" void kernel_launch(void* const* d_in, const int* in_sizes, int n_in,
                              void* d_out, int out_size)
{
    const float* x        = (const float*)d_in[0];
    const int*   ei       = (const int*)  d_in[1];
    const float* gat_W0   = (const float*)d_in[3];
    const float* gat_W12  = (const float*)d_in[4];
    const float* att_src  = (const float*)d_in[5];
    const float* att_dst  = (const float*)d_in[6];
    const float* gat_bias = (const float*)d_in[7];
    const float* qkv_w    = (const float*)d_in[8];
    const float* qkv_b    = (const float*)d_in[9];
    const float* out_w    = (const float*)d_in[10];
    const float* out_b    = (const float*)d_in[11];
    const float* ln1_w    = (const float*)d_in[12];
    const float* ln1_b    = (const float*)d_in[13];
    const float* ln2_w    = (const float*)d_in[14];
    const float* ln2_b    = (const float*)d_in[15];
    const float* ff1_w    = (const float*)d_in[16];
    const float* ff1_b    = (const float*)d_in[17];
    const float* ff2_w    = (const float*)d_in[18];
    const float* ff2_b    = (const float*)d_in[19];
    const float* pred_w   = (const float*)d_in[20];
    const float* pred_b   = (const float*)d_in[21];

    const int E = in_sizes[1] / 2;
    const int Etot = E + NN;
    const int* src = ei;
    const int* dst = ei + E;

    float *hl, *h0, *h1, *as_, *ad_, *pe, *qkv, *attn, *tmp, *ff;
    cudaGetSymbolAddress((void**)&hl,   g_hl);
    cudaGetSymbolAddress((void**)&h0,   g_h0);
    cudaGetSymbolAddress((void**)&h1,   g_h1);
    cudaGetSymbolAddress((void**)&as_,  g_as);
    cudaGetSymbolAddress((void**)&ad_,  g_ad);
    cudaGetSymbolAddress((void**)&pe,   g_pe);
    cudaGetSymbolAddress((void**)&qkv,  g_qkv);
    cudaGetSymbolAddress((void**)&attn, g_attn);
    cudaGetSymbolAddress((void**)&tmp,  g_tmp);
    cudaGetSymbolAddress((void**)&ff,   g_ff);

    const int eb = (Etot + 255) / 256;

    // CSR build (once)
    csr_zero_kernel<<<(NN + 255) / 256, 256>>>();
    csr_hist_kernel<<<eb, 256>>>(dst, E, Etot);
    csr_scan_kernel<<<1, 1024>>>();
    csr_fill_kernel<<<eb, 256>>>(src, dst, E, Etot);

    auto gat_layer = [&](const float* in, int Din, const float* W,
                         const float* atts, const float* attd, const float* bias,
                         float* outp) {
        tgemm_kernel<0><<<dim3(DD / 128, NN / 128), 256>>>(in, W, nullptr, hl, NN, DD, Din);
        gat_coef_kernel<<<(NN * HH) / 256, 256>>>(hl, atts, attd, as_, ad_);
        gat_edge_p_kernel<<<eb, 256>>>(Etot, as_, ad_, pe);
        gat_gather_kernel<<<NN, 256>>>(hl, pe, bias, outp);
    };

    gat_layer(x,  INC, gat_W0,            att_src,           att_dst,           gat_bias,          h0);
    gat_layer(h0, DD,  gat_W12,           att_src + HH * CC, att_dst + HH * CC, gat_bias + DD,     h1);
    gat_layer(h1, DD,  gat_W12 + DD * DD, att_src + 2*HH*CC, att_dst + 2*HH*CC, gat_bias + 2 * DD, h0);

    for (int l = 0; l < 2; l++) {
        const float* qw  = qkv_w + (size_t)l * 3 * DD * DD;
        const float* qb  = qkv_b + l * 3 * DD;
        const float* ow  = out_w + (size_t)l * DD * DD;
        const float* ob  = out_b + l * DD;
        const float* l1w = ln1_w + l * DD, * l1b = ln1_b + l * DD;
        const float* l2w = ln2_w + l * DD, * l2b = ln2_b + l * DD;
        const float* f1w = ff1_w + (size_t)l * DFF * DD;
        const float* f1b = ff1_b + l * DFF;
        const float* f2w = ff2_w + (size_t)l * DD * DFF;
        const float* f2b = ff2_b + l * DD;

        tgemm_kernel<1><<<dim3(3 * DD / 128, NN / 128), 256>>>(h0, qw, qb, qkv, NN, 3 * DD, DD);
        attn_mma_kernel<<<dim3(BB * HH, LL / 64), 128>>>(qkv, attn);
        tgemm_kernel<1><<<dim3(DD / 128, NN / 128), 256>>>(attn, ow, ob, tmp, NN, DD, DD);
        ln_res_kernel<<<NN, 256>>>(h0, tmp, l1w, l1b, h1);
        tgemm_kernel<2><<<dim3(DFF / 128, NN / 128), 256>>>(h1, f1w, f1b, ff, NN, DFF, DD);
        tgemm_kernel<1><<<dim3(DD / 128, NN / 128), 256>>>(ff, f2w, f2b, tmp, NN, DD, DFF);
        ln_res_kernel<<<NN, 256>>>(h1, tmp, l2w, l2b, h0);
    }

    pred_kernel<<<NN / 8, 256>>>(h0, pred_w, pred_b, (float*)d_out);
}

// round 6
// speedup vs baseline: 3.5798x; 1.0132x over previous
#include <cuda_runtime.h>
#include <math.h>

#define NN   8192
#define BB   8
#define LL   1024
#define INC  64
#define HH   8
#define CC   32
#define DD   256
#define DFF  2048
#define EMAX 262144
#define ETOTMAX (EMAX + NN)

#define TG_SMEM (2 * 2 * 128 * 36 * 4)   // 73728 bytes

// ---------------- scratch (device globals; no runtime allocation) ----------------
__device__ float g_hl  [NN * DD];
__device__ float g_h0  [NN * DD];
__device__ float g_h1  [NN * DD];
__device__ float g_as  [NN * HH];
__device__ float g_ad  [NN * HH];
__device__ float g_pe  [ETOTMAX * HH];
__device__ float g_qkv [NN * 3 * DD];
__device__ float g_attn[NN * DD];
__device__ float g_tmp [NN * DD];
__device__ float g_ff  [NN * DFF];
// CSR (built once per launch)
__device__ int   g_deg [NN];
__device__ int   g_off [NN + 1];
__device__ int   g_pos [NN];
__device__ int   g_esrc[ETOTMAX];
__device__ int   g_edst[ETOTMAX];

// ---------------- helpers ----------------
__device__ __forceinline__ float f2tf_f(float f) {
    unsigned u;
    asm("cvt.rna.tf32.f32 %0, %1;" : "=r"(u) : "f"(f));
    return __uint_as_float(u);
}

__device__ __forceinline__ void mma8(float* d, const unsigned* a, const unsigned* b) {
    asm volatile(
        "mma.sync.aligned.m16n8k8.row.col.f32.tf32.tf32.f32 "
        "{%0,%1,%2,%3},{%4,%5,%6,%7},{%8,%9},{%0,%1,%2,%3};"
        : "+f"(d[0]), "+f"(d[1]), "+f"(d[2]), "+f"(d[3])
        : "r"(a[0]), "r"(a[1]), "r"(a[2]), "r"(a[3]), "r"(b[0]), "r"(b[1]));
}

// ---------------- double-buffered tensor-core GEMM --------------------------------
// C[M,Nn] = A[M,K] * W[Nn,K]^T (+bias)(+relu); tf32 single-pass.
// BM=128, BN=128, BK=32; 2 smem stages; one __syncthreads per k-tile.
template<int BIASMODE>
__global__ void __launch_bounds__(256) tgemm_kernel(
    const float* __restrict__ A, const float* __restrict__ W,
    const float* __restrict__ bias, float* __restrict__ C,
    int M, int Nn, int K)
{
    extern __shared__ __align__(16) float sm[];
    float (*As)[36] = (float(*)[36])sm;                    // [2*128][36]
    float (*Bs)[36] = (float(*)[36])(sm + 2 * 128 * 36);   // [2*128][36]

    const int bm = blockIdx.y * 128;
    const int bn = blockIdx.x * 128;
    const int tid = threadIdx.x;
    const int warp = tid >> 5, lane = tid & 31;
    const int wm = warp & 3, wn = warp >> 2;
    const int lg = lane >> 2;
    const int lt = lane & 3;

    int lrow[4], lc4[4];
#pragma unroll
    for (int i = 0; i < 4; i++) {
        int f4 = tid + i * 256;
        lrow[i] = f4 >> 3;
        lc4[i] = (f4 & 7) << 2;
    }

    float acc[2][8][4];
#pragma unroll
    for (int mt = 0; mt < 2; mt++)
#pragma unroll
        for (int nt = 0; nt < 8; nt++)
#pragma unroll
            for (int r = 0; r < 4; r++) acc[mt][nt][r] = 0.0f;

    // preload stage 0
#pragma unroll
    for (int i = 0; i < 4; i++) {
        float4 av = *(const float4*)&A[(size_t)(bm + lrow[i]) * K + lc4[i]];
        float4 bv = *(const float4*)&W[(size_t)(bn + lrow[i]) * K + lc4[i]];
        av.x = f2tf_f(av.x); av.y = f2tf_f(av.y);
        av.z = f2tf_f(av.z); av.w = f2tf_f(av.w);
        bv.x = f2tf_f(bv.x); bv.y = f2tf_f(bv.y);
        bv.z = f2tf_f(bv.z); bv.w = f2tf_f(bv.w);
        *(float4*)&As[lrow[i]][lc4[i]] = av;
        *(float4*)&Bs[lrow[i]][lc4[i]] = bv;
    }
    __syncthreads();

    const int nk = K >> 5;
    for (int t = 0; t < nk; t++) {
        const int st = (t & 1) * 128;
        const int sn = ((t & 1) ^ 1) * 128;
        const bool more = (t + 1 < nk);
        float4 pa[4], pb[4];
        if (more) {
            const int k0 = (t + 1) << 5;
#pragma unroll
            for (int i = 0; i < 4; i++) {
                pa[i] = *(const float4*)&A[(size_t)(bm + lrow[i]) * K + k0 + lc4[i]];
                pb[i] = *(const float4*)&W[(size_t)(bn + lrow[i]) * K + k0 + lc4[i]];
            }
        }
#pragma unroll
        for (int kk = 0; kk < 32; kk += 8) {
            unsigned ah[2][4], bf[8][2];
            const int c = kk + lt;
#pragma unroll
            for (int mt = 0; mt < 2; mt++) {
                int r = st + wm * 32 + mt * 16 + lg;
                ah[mt][0] = __float_as_uint(As[r][c]);
                ah[mt][1] = __float_as_uint(As[r + 8][c]);
                ah[mt][2] = __float_as_uint(As[r][c + 4]);
                ah[mt][3] = __float_as_uint(As[r + 8][c + 4]);
            }
#pragma unroll
            for (int nt = 0; nt < 8; nt++) {
                int n = st + wn * 64 + nt * 8 + lg;
                bf[nt][0] = __float_as_uint(Bs[n][c]);
                bf[nt][1] = __float_as_uint(Bs[n][c + 4]);
            }
#pragma unroll
            for (int mt = 0; mt < 2; mt++)
#pragma unroll
                for (int nt = 0; nt < 8; nt++)
                    mma8(acc[mt][nt], ah[mt], bf[nt]);
        }
        if (more) {
#pragma unroll
            for (int i = 0; i < 4; i++) {
                float4 av = pa[i], bv = pb[i];
                av.x = f2tf_f(av.x); av.y = f2tf_f(av.y);
                av.z = f2tf_f(av.z); av.w = f2tf_f(av.w);
                bv.x = f2tf_f(bv.x); bv.y = f2tf_f(bv.y);
                bv.z = f2tf_f(bv.z); bv.w = f2tf_f(bv.w);
                *(float4*)&As[sn + lrow[i]][lc4[i]] = av;
                *(float4*)&Bs[sn + lrow[i]][lc4[i]] = bv;
            }
        }
        __syncthreads();
    }

#pragma unroll
    for (int mt = 0; mt < 2; mt++) {
#pragma unroll
        for (int nt = 0; nt < 8; nt++) {
            int row = bm + wm * 32 + mt * 16 + lg;
            int col = bn + wn * 64 + nt * 8 + (lt << 1);
            float b0 = 0.f, b1 = 0.f;
            if (BIASMODE > 0) { b0 = bias[col]; b1 = bias[col + 1]; }
            float v0 = acc[mt][nt][0] + b0, v1 = acc[mt][nt][1] + b1;
            float v2 = acc[mt][nt][2] + b0, v3 = acc[mt][nt][3] + b1;
            if (BIASMODE == 2) {
                v0 = fmaxf(v0, 0.f); v1 = fmaxf(v1, 0.f);
                v2 = fmaxf(v2, 0.f); v3 = fmaxf(v3, 0.f);
            }
            *(float2*)&C[(size_t)row * Nn + col] = make_float2(v0, v1);
            *(float2*)&C[(size_t)(row + 8) * Nn + col] = make_float2(v2, v3);
        }
    }
}

// ---------------- CSR build (once per launch) ----------------
__global__ void csr_zero_kernel() {
    int i = blockIdx.x * blockDim.x + threadIdx.x;
    if (i < NN) g_deg[i] = 0;
}

__global__ void csr_hist_kernel(const int* __restrict__ dst, int E, int Etot) {
    int e = blockIdx.x * blockDim.x + threadIdx.x;
    if (e >= Etot) return;
    int d = (e < E) ? dst[e] : (e - E);
    atomicAdd(&g_deg[d], 1);
}

__global__ void __launch_bounds__(1024) csr_scan_kernel() {
    __shared__ int ts[1024];
    int t = threadIdx.x;
    int base = t * 8;
    int local[8];
    int s = 0;
#pragma unroll
    for (int j = 0; j < 8; j++) { local[j] = s; s += g_deg[base + j]; }
    ts[t] = s;
    __syncthreads();
    for (int off = 1; off < 1024; off <<= 1) {
        int v = (t >= off) ? ts[t - off] : 0;
        __syncthreads();
        ts[t] += v;
        __syncthreads();
    }
    int prefix = (t == 0) ? 0 : ts[t - 1];
#pragma unroll
    for (int j = 0; j < 8; j++) {
        int o = prefix + local[j];
        g_off[base + j] = o;
        g_pos[base + j] = o;
    }
    if (t == 1023) g_off[NN] = ts[1023];
}

__global__ void csr_fill_kernel(const int* __restrict__ src, const int* __restrict__ dst,
                                int E, int Etot) {
    int e = blockIdx.x * blockDim.x + threadIdx.x;
    if (e >= Etot) return;
    int s, d;
    if (e < E) { s = src[e]; d = dst[e]; } else { s = d = e - E; }
    int p = atomicAdd(&g_pos[d], 1);
    g_esrc[p] = s;
    g_edst[p] = d;
}

// ---------------- GAT kernels ----------------
__global__ void gat_coef_kernel(const float* __restrict__ hl,
                                const float* __restrict__ atts,
                                const float* __restrict__ attd,
                                float* __restrict__ as_, float* __restrict__ ad_)
{
    int t = blockIdx.x * blockDim.x + threadIdx.x;
    if (t >= NN * HH) return;
    int n = t >> 3, h = t & 7;
    const float4* hp = reinterpret_cast<const float4*>(&hl[(size_t)n * DD + h * 32]);
    const float4* sp = reinterpret_cast<const float4*>(&atts[h * 32]);
    const float4* dp = reinterpret_cast<const float4*>(&attd[h * 32]);
    float ss = 0.f, dd = 0.f;
#pragma unroll
    for (int w = 0; w < 8; w++) {
        float4 hv = hp[w], sv = sp[w], dv = dp[w];
        ss += hv.x * sv.x + hv.y * sv.y + hv.z * sv.z + hv.w * sv.w;
        dd += hv.x * dv.x + hv.y * dv.y + hv.z * dv.z + hv.w * dv.w;
    }
    as_[t] = ss;
    ad_[t] = dd;
}

__global__ void gat_edge_p_kernel(int Etot,
                                  const float* __restrict__ as_,
                                  const float* __restrict__ ad_,
                                  float* __restrict__ pe)
{
    int i = blockIdx.x * blockDim.x + threadIdx.x;
    if (i >= Etot) return;
    int s = g_esrc[i], d = g_edst[i];
    float4 s0 = *(const float4*)&as_[s * 8];
    float4 s1 = *(const float4*)&as_[s * 8 + 4];
    float4 d0 = *(const float4*)&ad_[d * 8];
    float4 d1 = *(const float4*)&ad_[d * 8 + 4];
    float a[8] = {s0.x + d0.x, s0.y + d0.y, s0.z + d0.z, s0.w + d0.w,
                  s1.x + d1.x, s1.y + d1.y, s1.z + d1.z, s1.w + d1.w};
#pragma unroll
    for (int h = 0; h < 8; h++) {
        float t = a[h];
        t = (t > 0.f) ? t : 0.2f * t;
        a[h] = __expf(t);
    }
    *(float4*)&pe[(size_t)i * 8]     = make_float4(a[0], a[1], a[2], a[3]);
    *(float4*)&pe[(size_t)i * 8 + 4] = make_float4(a[4], a[5], a[6], a[7]);
}

__global__ void __launch_bounds__(256) gat_gather_kernel(
    const float* __restrict__ hl, const float* __restrict__ pe,
    const float* __restrict__ bias, float* __restrict__ out)
{
    const int d = blockIdx.x;
    const int h = threadIdx.x >> 5, lane = threadIdx.x & 31;
    const int beg = g_off[d], end = g_off[d + 1];
    const int hc = h * 32 + lane;

    float acc0 = 0.f, acc1 = 0.f, acc2 = 0.f, acc3 = 0.f;
    float ss = 0.f;
    int i = beg;
    for (; i + 4 <= end; i += 4) {
        int s0 = g_esrc[i], s1 = g_esrc[i + 1], s2 = g_esrc[i + 2], s3 = g_esrc[i + 3];
        float p0 = pe[(size_t)i * 8 + h];
        float p1 = pe[(size_t)(i + 1) * 8 + h];
        float p2 = pe[(size_t)(i + 2) * 8 + h];
        float p3 = pe[(size_t)(i + 3) * 8 + h];
        float v0 = hl[(size_t)s0 * DD + hc];
        float v1 = hl[(size_t)s1 * DD + hc];
        float v2 = hl[(size_t)s2 * DD + hc];
        float v3 = hl[(size_t)s3 * DD + hc];
        ss += (p0 + p1) + (p2 + p3);
        acc0 = fmaf(p0, v0, acc0);
        acc1 = fmaf(p1, v1, acc1);
        acc2 = fmaf(p2, v2, acc2);
        acc3 = fmaf(p3, v3, acc3);
    }
    for (; i < end; i++) {
        int s0 = g_esrc[i];
        float p0 = pe[(size_t)i * 8 + h];
        ss += p0;
        acc0 = fmaf(p0, hl[(size_t)s0 * DD + hc], acc0);
    }
    float acc = (acc0 + acc1) + (acc2 + acc3);
    out[(size_t)d * DD + hc] = fmaxf(acc / ss + bias[hc], 0.f);
}

// ---------------- MMA flash-attention ----------------
__global__ void __launch_bounds__(128) attn_mma_kernel(const float* __restrict__ qkv,
                                                       float* __restrict__ out)
{
    __shared__ __align__(16) float Qs[64][36];
    __shared__ __align__(16) float Ks[64][36];
    __shared__ __align__(16) float Vt[32][68];
    __shared__ __align__(16) float Ps[64][68];

    const int bh = blockIdx.x, b = bh >> 3, h = bh & 7;
    const int qt = blockIdx.y;
    const int tid = threadIdx.x;
    const int warp = tid >> 5, lane = tid & 31;
    const int lg = lane >> 2, lt = lane & 3;
    const float* base = qkv + (size_t)b * LL * 768;
    const float scale = 0.17677669529663687f;

#pragma unroll
    for (int i = 0; i < 4; i++) {
        int idx = tid + i * 128;
        int row = idx >> 3, c4 = (idx & 7) << 2;
        float4 v = *(const float4*)(base + (size_t)(qt * 64 + row) * 768 + h * 32 + c4);
        Qs[row][c4 + 0] = f2tf_f(v.x * scale);
        Qs[row][c4 + 1] = f2tf_f(v.y * scale);
        Qs[row][c4 + 2] = f2tf_f(v.z * scale);
        Qs[row][c4 + 3] = f2tf_f(v.w * scale);
    }

    float m0 = -1e30f, m1 = -1e30f, l0 = 0.f, l1 = 0.f;
    float o[4][4];
#pragma unroll
    for (int nt = 0; nt < 4; nt++)
#pragma unroll
        for (int r = 0; r < 4; r++) o[nt][r] = 0.f;

    const int r0 = warp * 16 + lg;

    for (int kt = 0; kt < 16; kt++) {
        __syncthreads();
#pragma unroll
        for (int i = 0; i < 4; i++) {
            int idx = tid + i * 128;
            int row = idx >> 3, c4 = (idx & 7) << 2;
            const float* kp = base + (size_t)(kt * 64 + row) * 768 + 256 + h * 32 + c4;
            float4 kv = *(const float4*)kp;
            Ks[row][c4 + 0] = f2tf_f(kv.x);
            Ks[row][c4 + 1] = f2tf_f(kv.y);
            Ks[row][c4 + 2] = f2tf_f(kv.z);
            Ks[row][c4 + 3] = f2tf_f(kv.w);
            float4 vv = *(const float4*)(kp + 256);
            Vt[c4 + 0][row] = f2tf_f(vv.x);
            Vt[c4 + 1][row] = f2tf_f(vv.y);
            Vt[c4 + 2][row] = f2tf_f(vv.z);
            Vt[c4 + 3][row] = f2tf_f(vv.w);
        }
        __syncthreads();

        float s[8][4];
#pragma unroll
        for (int nt = 0; nt < 8; nt++)
#pragma unroll
            for (int r = 0; r < 4; r++) s[nt][r] = 0.f;
#pragma unroll
        for (int kk = 0; kk < 4; kk++) {
            const int c = kk * 8 + lt;
            unsigned a[4];
            a[0] = __float_as_uint(Qs[r0][c]);
            a[1] = __float_as_uint(Qs[r0 + 8][c]);
            a[2] = __float_as_uint(Qs[r0][c + 4]);
            a[3] = __float_as_uint(Qs[r0 + 8][c + 4]);
#pragma unroll
            for (int nt = 0; nt < 8; nt++) {
                unsigned bb[2];
                bb[0] = __float_as_uint(Ks[nt * 8 + lg][c]);
                bb[1] = __float_as_uint(Ks[nt * 8 + lg][c + 4]);
                mma8(s[nt], a, bb);
            }
        }

        float mx0 = -1e30f, mx1 = -1e30f;
#pragma unroll
        for (int nt = 0; nt < 8; nt++) {
            mx0 = fmaxf(mx0, fmaxf(s[nt][0], s[nt][1]));
            mx1 = fmaxf(mx1, fmaxf(s[nt][2], s[nt][3]));
        }
        mx0 = fmaxf(mx0, __shfl_xor_sync(0xffffffffu, mx0, 1));
        mx0 = fmaxf(mx0, __shfl_xor_sync(0xffffffffu, mx0, 2));
        mx1 = fmaxf(mx1, __shfl_xor_sync(0xffffffffu, mx1, 1));
        mx1 = fmaxf(mx1, __shfl_xor_sync(0xffffffffu, mx1, 2));
        float nm0 = fmaxf(m0, mx0), nm1 = fmaxf(m1, mx1);
        float c0 = __expf(m0 - nm0), c1 = __expf(m1 - nm1);
        m0 = nm0; m1 = nm1;

        float ps0 = 0.f, ps1 = 0.f;
#pragma unroll
        for (int nt = 0; nt < 8; nt++) {
            float p0 = __expf(s[nt][0] - m0);
            float p1 = __expf(s[nt][1] - m0);
            float p2 = __expf(s[nt][2] - m1);
            float p3 = __expf(s[nt][3] - m1);
            ps0 += p0 + p1;
            ps1 += p2 + p3;
            int col = nt * 8 + (lt << 1);
            Ps[r0][col]     = f2tf_f(p0);
            Ps[r0][col + 1] = f2tf_f(p1);
            Ps[r0 + 8][col]     = f2tf_f(p2);
            Ps[r0 + 8][col + 1] = f2tf_f(p3);
        }
        ps0 += __shfl_xor_sync(0xffffffffu, ps0, 1);
        ps0 += __shfl_xor_sync(0xffffffffu, ps0, 2);
        ps1 += __shfl_xor_sync(0xffffffffu, ps1, 1);
        ps1 += __shfl_xor_sync(0xffffffffu, ps1, 2);
        l0 = l0 * c0 + ps0;
        l1 = l1 * c1 + ps1;
#pragma unroll
        for (int nt = 0; nt < 4; nt++) {
            o[nt][0] *= c0; o[nt][1] *= c0;
            o[nt][2] *= c1; o[nt][3] *= c1;
        }
        __syncwarp();

#pragma unroll
        for (int kk = 0; kk < 8; kk++) {
            const int c = kk * 8 + lt;
            unsigned a[4];
            a[0] = __float_as_uint(Ps[r0][c]);
            a[1] = __float_as_uint(Ps[r0 + 8][c]);
            a[2] = __float_as_uint(Ps[r0][c + 4]);
            a[3] = __float_as_uint(Ps[r0 + 8][c + 4]);
#pragma unroll
            for (int nt = 0; nt < 4; nt++) {
                unsigned bb[2];
                bb[0] = __float_as_uint(Vt[nt * 8 + lg][c]);
                bb[1] = __float_as_uint(Vt[nt * 8 + lg][c + 4]);
                mma8(o[nt], a, bb);
            }
        }
    }

    float inv0 = 1.0f / l0, inv1 = 1.0f / l1;
    int q0 = qt * 64 + r0;
    float* op = out + (size_t)(b * LL + q0) * DD + h * 32;
#pragma unroll
    for (int nt = 0; nt < 4; nt++) {
        int col = nt * 8 + (lt << 1);
        *(float2*)(op + col) = make_float2(o[nt][0] * inv0, o[nt][1] * inv0);
        *(float2*)(op + 8 * DD + col) = make_float2(o[nt][2] * inv1, o[nt][3] * inv1);
    }
}

// ---------------- residual + LayerNorm ----------------
__global__ void __launch_bounds__(256) ln_res_kernel(
    const float* __restrict__ x, const float* __restrict__ r,
    const float* __restrict__ w, const float* __restrict__ b,
    float* __restrict__ y)
{
    int row = blockIdx.x, t = threadIdx.x;
    size_t i = (size_t)row * DD + t;
    float v = x[i] + r[i];
    float s1 = v, s2 = v * v;
#pragma unroll
    for (int o = 16; o; o >>= 1) {
        s1 += __shfl_xor_sync(0xffffffffu, s1, o);
        s2 += __shfl_xor_sync(0xffffffffu, s2, o);
    }
    __shared__ float a1[8], a2[8];
    int wid = t >> 5, lane = t & 31;
    if (lane == 0) { a1[wid] = s1; a2[wid] = s2; }
    __syncthreads();
    float S1 = 0.f, S2 = 0.f;
#pragma unroll
    for (int k = 0; k < 8; k++) { S1 += a1[k]; S2 += a2[k]; }
    float mu = S1 * (1.0f / DD);
    float var = S2 * (1.0f / DD) - mu * mu;
    y[i] = (v - mu) * rsqrtf(var + 1e-5f) * w[t] + b[t];
}

// ---------------- final prediction ----------------
__global__ void __launch_bounds__(256) pred_kernel(
    const float* __restrict__ x, const float* __restrict__ pw,
    const float* __restrict__ pb, float* __restrict__ out)
{
    int n = blockIdx.x * 8 + (threadIdx.x >> 5);
    int lane = threadIdx.x & 31;
    const float* xr = x + (size_t)n * DD;
    float xv[8];
#pragma unroll
    for (int k = 0; k < 8; k++) xv[k] = xr[lane + 32 * k];
    float a0 = 0.f, a1 = 0.f, a2 = 0.f;
#pragma unroll
    for (int k = 0; k < 8; k++) {
        int c = lane + 32 * k;
        a0 += xv[k] * pw[0 * DD + c];
        a1 += xv[k] * pw[1 * DD + c];
        a2 += xv[k] * pw[2 * DD + c];
    }
#pragma unroll
    for (int o = 16; o; o >>= 1) {
        a0 += __shfl_xor_sync(0xffffffffu, a0, o);
        a1 += __shfl_xor_sync(0xffffffffu, a1, o);
        a2 += __shfl_xor_sync(0xffffffffu, a2, o);
    }
    if (lane == 0) {
        out[n * 3 + 0] = a0 + pb[0];
        out[n * 3 + 1] = a1 + pb[1];
        out[n * 3 + 2] = a2 + pb[2];
    }
}

// ---------------- host orchestration ----------------
extern "C" void kernel_launch(void* const* d_in, const int* in_sizes, int n_in,
                              void* d_out, int out_size)
{
    const float* x        = (const float*)d_in[0];
    const int*   ei       = (const int*)  d_in[1];
    const float* gat_W0   = (const float*)d_in[3];
    const float* gat_W12  = (const float*)d_in[4];
    const float* att_src  = (const float*)d_in[5];
    const float* att_dst  = (const float*)d_in[6];
    const float* gat_bias = (const float*)d_in[7];
    const float* qkv_w    = (const float*)d_in[8];
    const float* qkv_b    = (const float*)d_in[9];
    const float* out_w    = (const float*)d_in[10];
    const float* out_b    = (const float*)d_in[11];
    const float* ln1_w    = (const float*)d_in[12];
    const float* ln1_b    = (const float*)d_in[13];
    const float* ln2_w    = (const float*)d_in[14];
    const float* ln2_b    = (const float*)d_in[15];
    const float* ff1_w    = (const float*)d_in[16];
    const float* ff1_b    = (const float*)d_in[17];
    const float* ff2_w    = (const float*)d_in[18];
    const float* ff2_b    = (const float*)d_in[19];
    const float* pred_w   = (const float*)d_in[20];
    const float* pred_b   = (const float*)d_in[21];

    const int E = in_sizes[1] / 2;
    const int Etot = E + NN;
    const int* src = ei;
    const int* dst = ei + E;

    float *hl, *h0, *h1, *as_, *ad_, *pe, *qkv, *attn, *tmp, *ff;
    cudaGetSymbolAddress((void**)&hl,   g_hl);
    cudaGetSymbolAddress((void**)&h0,   g_h0);
    cudaGetSymbolAddress((void**)&h1,   g_h1);
    cudaGetSymbolAddress((void**)&as_,  g_as);
    cudaGetSymbolAddress((void**)&ad_,  g_ad);
    cudaGetSymbolAddress((void**)&pe,   g_pe);
    cudaGetSymbolAddress((void**)&qkv,  g_qkv);
    cudaGetSymbolAddress((void**)&attn, g_attn);
    cudaGetSymbolAddress((void**)&tmp,  g_tmp);
    cudaGetSymbolAddress((void**)&ff,   g_ff);

    cudaFuncSetAttribute(tgemm_kernel<0>, cudaFuncAttributeMaxDynamicSharedMemorySize, TG_SMEM);
    cudaFuncSetAttribute(tgemm_kernel<1>, cudaFuncAttributeMaxDynamicSharedMemorySize, TG_SMEM);
    cudaFuncSetAttribute(tgemm_kernel<2>, cudaFuncAttributeMaxDynamicSharedMemorySize, TG_SMEM);

    const int eb = (Etot + 255) / 256;

    // CSR build (once)
    csr_zero_kernel<<<(NN + 255) / 256, 256>>>();
    csr_hist_kernel<<<eb, 256>>>(dst, E, Etot);
    csr_scan_kernel<<<1, 1024>>>();
    csr_fill_kernel<<<eb, 256>>>(src, dst, E, Etot);

    auto gat_layer = [&](const float* in, int Din, const float* W,
                         const float* atts, const float* attd, const float* bias,
                         float* outp) {
        tgemm_kernel<0><<<dim3(DD / 128, NN / 128), 256, TG_SMEM>>>(in, W, nullptr, hl, NN, DD, Din);
        gat_coef_kernel<<<(NN * HH) / 256, 256>>>(hl, atts, attd, as_, ad_);
        gat_edge_p_kernel<<<eb, 256>>>(Etot, as_, ad_, pe);
        gat_gather_kernel<<<NN, 256>>>(hl, pe, bias, outp);
    };

    gat_layer(x,  INC, gat_W0,            att_src,           att_dst,           gat_bias,          h0);
    gat_layer(h0, DD,  gat_W12,           att_src + HH * CC, att_dst + HH * CC, gat_bias + DD,     h1);
    gat_layer(h1, DD,  gat_W12 + DD * DD, att_src + 2*HH*CC, att_dst + 2*HH*CC, gat_bias + 2 * DD, h0);

    for (int l = 0; l < 2; l++) {
        const float* qw  = qkv_w + (size_t)l * 3 * DD * DD;
        const float* qb  = qkv_b + l * 3 * DD;
        const float* ow  = out_w + (size_t)l * DD * DD;
        const float* ob  = out_b + l * DD;
        const float* l1w = ln1_w + l * DD, * l1b = ln1_b + l * DD;
        const float* l2w = ln2_w + l * DD, * l2b = ln2_b + l * DD;
        const float* f1w = ff1_w + (size_t)l * DFF * DD;
        const float* f1b = ff1_b + l * DFF;
        const float* f2w = ff2_w + (size_t)l * DD * DFF;
        const float* f2b = ff2_b + l * DD;

        tgemm_kernel<1><<<dim3(3 * DD / 128, NN / 128), 256, TG_SMEM>>>(h0, qw, qb, qkv, NN, 3 * DD, DD);
        attn_mma_kernel<<<dim3(BB * HH, LL / 64), 128>>>(qkv, attn);
        tgemm_kernel<1><<<dim3(DD / 128, NN / 128), 256, TG_SMEM>>>(attn, ow, ob, tmp, NN, DD, DD);
        ln_res_kernel<<<NN, 256>>>(h0, tmp, l1w, l1b, h1);
        tgemm_kernel<2><<<dim3(DFF / 128, NN / 128), 256, TG_SMEM>>>(h1, f1w, f1b, ff, NN, DFF, DD);
        tgemm_kernel<1><<<dim3(DD / 128, NN / 128), 256, TG_SMEM>>>(ff, f2w, f2b, tmp, NN, DD, DFF);
        ln_res_kernel<<<NN, 256>>>(h1, tmp, l2w, l2b, h0);
    }

    pred_kernel<<<NN / 8, 256>>>(h0, pred_w, pred_b, (float*)d_out);
}

// round 7
// speedup vs baseline: 3.8337x; 1.0709x over previous
#include <cuda_runtime.h>
#include <math.h>

#define NN   8192
#define BB   8
#define LL   1024
#define INC  64
#define HH   8
#define CC   32
#define DD   256
#define DFF  2048
#define EMAX 262144
#define ETOTMAX (EMAX + NN)

#define TG_STG   (256 * 36)              // floats per stage (A 128x36 + B 128x36)
#define TG_SMEM3 (3 * TG_STG * 4)        // 110592 B
#define TL_STG   (320 * 36)              // A 64x36 + B 256x36
#define TL_SMEM3 (3 * TL_STG * 4)        // 138240 B

// ---------------- scratch (device globals; no runtime allocation) ----------------
__device__ float g_hl  [NN * DD];
__device__ float g_h0  [NN * DD];
__device__ float g_h1  [NN * DD];
__device__ float g_as  [NN * HH];
__device__ float g_ad  [NN * HH];
__device__ float g_pe  [ETOTMAX * HH];
__device__ float g_qkv [NN * 3 * DD];
__device__ float g_attn[NN * DD];
__device__ float g_ff  [NN * DFF];
// CSR (built once per launch)
__device__ int   g_deg [NN];
__device__ int   g_off [NN + 1];
__device__ int   g_pos [NN];
__device__ int   g_esrc[ETOTMAX];
__device__ int   g_edst[ETOTMAX];

// ---------------- helpers ----------------
__device__ __forceinline__ float f2tf_f(float f) {
    unsigned u;
    asm("cvt.rna.tf32.f32 %0, %1;" : "=r"(u) : "f"(f));
    return __uint_as_float(u);
}

__device__ __forceinline__ void mma8(float* d, const unsigned* a, const unsigned* b) {
    asm volatile(
        "mma.sync.aligned.m16n8k8.row.col.f32.tf32.tf32.f32 "
        "{%0,%1,%2,%3},{%4,%5,%6,%7},{%8,%9},{%0,%1,%2,%3};"
        : "+f"(d[0]), "+f"(d[1]), "+f"(d[2]), "+f"(d[3])
        : "r"(a[0]), "r"(a[1]), "r"(a[2]), "r"(a[3]), "r"(b[0]), "r"(b[1]));
}

#define CP16(dst_u32, src_ptr) \
    asm volatile("cp.async.cg.shared.global [%0], [%1], 16;\n" :: "r"(dst_u32), "l"(src_ptr))
#define CP_COMMIT() asm volatile("cp.async.commit_group;\n" ::)
#define CP_WAIT1()  asm volatile("cp.async.wait_group 1;\n" ::)

// ---------------- cp.async 3-stage tensor-core GEMM -------------------------------
// C[M,Nn] = A[M,K] * W[Nn,K]^T (+bias)(+relu); operands raw f32 (mma truncates).
// Output rounded to tf32 so downstream GEMMs see rna-rounded activations.
template<int BIASMODE>
__global__ void __launch_bounds__(256) tgemm_kernel(
    const float* __restrict__ A, const float* __restrict__ W,
    const float* __restrict__ bias, float* __restrict__ C,
    int M, int Nn, int K)
{
    extern __shared__ __align__(16) float sm[];
    unsigned sbase = (unsigned)__cvta_generic_to_shared(sm);

    const int bm = blockIdx.y * 128;
    const int bn = blockIdx.x * 128;
    const int tid = threadIdx.x;
    const int warp = tid >> 5, lane = tid & 31;
    const int wm = warp & 3, wn = warp >> 2;
    const int lg = lane >> 2, lt = lane & 3;

    int lrow[4], lc4[4];
#pragma unroll
    for (int i = 0; i < 4; i++) {
        int f4 = tid + i * 256;
        lrow[i] = f4 >> 3;
        lc4[i] = (f4 & 7) << 2;
    }

    float acc[2][8][4];
#pragma unroll
    for (int mt = 0; mt < 2; mt++)
#pragma unroll
        for (int nt = 0; nt < 8; nt++)
#pragma unroll
            for (int r = 0; r < 4; r++) acc[mt][nt][r] = 0.0f;

    const int nk = K >> 5;
    auto issue = [&](int t) {
        if (t < nk) {
            int k0 = t << 5;
            unsigned so = sbase + (unsigned)((t % 3) * TG_STG) * 4u;
#pragma unroll
            for (int i = 0; i < 4; i++) {
                const float* gA = A + (size_t)(bm + lrow[i]) * K + k0 + lc4[i];
                const float* gB = W + (size_t)(bn + lrow[i]) * K + k0 + lc4[i];
                CP16(so + (unsigned)(lrow[i] * 36 + lc4[i]) * 4u, gA);
                CP16(so + (unsigned)((128 * 36) + lrow[i] * 36 + lc4[i]) * 4u, gB);
            }
        }
        CP_COMMIT();
    };

    issue(0); issue(1);
    for (int t = 0; t < nk; t++) {
        CP_WAIT1();
        __syncthreads();
        issue(t + 2);
        const float* As = sm + (t % 3) * TG_STG;
        const float* Bs = As + 128 * 36;
#pragma unroll
        for (int kk = 0; kk < 32; kk += 8) {
            unsigned ah[2][4], bf[8][2];
            const int c = kk + lt;
#pragma unroll
            for (int mt = 0; mt < 2; mt++) {
                int r = wm * 32 + mt * 16 + lg;
                ah[mt][0] = __float_as_uint(As[r * 36 + c]);
                ah[mt][1] = __float_as_uint(As[(r + 8) * 36 + c]);
                ah[mt][2] = __float_as_uint(As[r * 36 + c + 4]);
                ah[mt][3] = __float_as_uint(As[(r + 8) * 36 + c + 4]);
            }
#pragma unroll
            for (int nt = 0; nt < 8; nt++) {
                int n = wn * 64 + nt * 8 + lg;
                bf[nt][0] = __float_as_uint(Bs[n * 36 + c]);
                bf[nt][1] = __float_as_uint(Bs[n * 36 + c + 4]);
            }
#pragma unroll
            for (int mt = 0; mt < 2; mt++)
#pragma unroll
                for (int nt = 0; nt < 8; nt++)
                    mma8(acc[mt][nt], ah[mt], bf[nt]);
        }
    }

#pragma unroll
    for (int mt = 0; mt < 2; mt++) {
#pragma unroll
        for (int nt = 0; nt < 8; nt++) {
            int row = bm + wm * 32 + mt * 16 + lg;
            int col = bn + wn * 64 + nt * 8 + (lt << 1);
            float b0 = 0.f, b1 = 0.f;
            if (BIASMODE > 0) { b0 = bias[col]; b1 = bias[col + 1]; }
            float v0 = acc[mt][nt][0] + b0, v1 = acc[mt][nt][1] + b1;
            float v2 = acc[mt][nt][2] + b0, v3 = acc[mt][nt][3] + b1;
            if (BIASMODE == 2) {
                v0 = fmaxf(v0, 0.f); v1 = fmaxf(v1, 0.f);
                v2 = fmaxf(v2, 0.f); v3 = fmaxf(v3, 0.f);
            }
            v0 = f2tf_f(v0); v1 = f2tf_f(v1);
            v2 = f2tf_f(v2); v3 = f2tf_f(v3);
            *(float2*)&C[(size_t)row * Nn + col] = make_float2(v0, v1);
            *(float2*)&C[(size_t)(row + 8) * Nn + col] = make_float2(v2, v3);
        }
    }
}

// ---------------- GEMM + residual + LayerNorm fused (Nn == 256) -------------------
// y = LN(res + A*W^T + bias) * lnw + lnb ; BM=64, BN=256 so a CTA owns full rows.
__global__ void __launch_bounds__(256) tgemm_ln_kernel(
    const float* __restrict__ A, const float* __restrict__ W,
    const float* __restrict__ bias, const float* __restrict__ res,
    const float* __restrict__ lnw, const float* __restrict__ lnb,
    float* __restrict__ Y, int M, int K)
{
    extern __shared__ __align__(16) float sm[];
    unsigned sbase = (unsigned)__cvta_generic_to_shared(sm);

    const int bm = blockIdx.y * 64;
    const int tid = threadIdx.x;
    const int warp = tid >> 5, lane = tid & 31;
    const int wm = warp & 1, wn = warp >> 1;     // 2 m-warps x 4 n-warps
    const int lg = lane >> 2, lt = lane & 3;

    // A loads: 2 float4/thread; B loads: 8 float4/thread
    int arow[2], ac4[2], brow[8], bc4[8];
#pragma unroll
    for (int i = 0; i < 2; i++) {
        int f4 = tid + i * 256;
        arow[i] = f4 >> 3; ac4[i] = (f4 & 7) << 2;
    }
#pragma unroll
    for (int i = 0; i < 8; i++) {
        int f4 = tid + i * 256;
        brow[i] = f4 >> 3; bc4[i] = (f4 & 7) << 2;
    }

    float acc[2][8][4];
#pragma unroll
    for (int mt = 0; mt < 2; mt++)
#pragma unroll
        for (int nt = 0; nt < 8; nt++)
#pragma unroll
            for (int r = 0; r < 4; r++) acc[mt][nt][r] = 0.0f;

    const int nk = K >> 5;
    auto issue = [&](int t) {
        if (t < nk) {
            int k0 = t << 5;
            unsigned so = sbase + (unsigned)((t % 3) * TL_STG) * 4u;
#pragma unroll
            for (int i = 0; i < 2; i++) {
                const float* gA = A + (size_t)(bm + arow[i]) * K + k0 + ac4[i];
                CP16(so + (unsigned)(arow[i] * 36 + ac4[i]) * 4u, gA);
            }
#pragma unroll
            for (int i = 0; i < 8; i++) {
                const float* gB = W + (size_t)brow[i] * K + k0 + bc4[i];
                CP16(so + (unsigned)((64 * 36) + brow[i] * 36 + bc4[i]) * 4u, gB);
            }
        }
        CP_COMMIT();
    };

    issue(0); issue(1);
    for (int t = 0; t < nk; t++) {
        CP_WAIT1();
        __syncthreads();
        issue(t + 2);
        const float* As = sm + (t % 3) * TL_STG;
        const float* Bs = As + 64 * 36;
#pragma unroll
        for (int kk = 0; kk < 32; kk += 8) {
            unsigned ah[2][4], bf[8][2];
            const int c = kk + lt;
#pragma unroll
            for (int mt = 0; mt < 2; mt++) {
                int r = wm * 32 + mt * 16 + lg;
                ah[mt][0] = __float_as_uint(As[r * 36 + c]);
                ah[mt][1] = __float_as_uint(As[(r + 8) * 36 + c]);
                ah[mt][2] = __float_as_uint(As[r * 36 + c + 4]);
                ah[mt][3] = __float_as_uint(As[(r + 8) * 36 + c + 4]);
            }
#pragma unroll
            for (int nt = 0; nt < 8; nt++) {
                int n = wn * 64 + nt * 8 + lg;
                bf[nt][0] = __float_as_uint(Bs[n * 36 + c]);
                bf[nt][1] = __float_as_uint(Bs[n * 36 + c + 4]);
            }
#pragma unroll
            for (int mt = 0; mt < 2; mt++)
#pragma unroll
                for (int nt = 0; nt < 8; nt++)
                    mma8(acc[mt][nt], ah[mt], bf[nt]);
        }
    }

    // ---- epilogue: add bias + residual, row LN over 256 cols ----
    __syncthreads();
    float* partS = sm;            // [4][64]
    float* partQ = sm + 256;      // [4][64]

    float rs[4] = {0.f, 0.f, 0.f, 0.f}, rq[4] = {0.f, 0.f, 0.f, 0.f};
#pragma unroll
    for (int mt = 0; mt < 2; mt++) {
        int rl = wm * 32 + mt * 16 + lg;
#pragma unroll
        for (int nt = 0; nt < 8; nt++) {
            int col = wn * 64 + nt * 8 + (lt << 1);
            float2 bb = *(const float2*)&bias[col];
            float2 ra = *(const float2*)&res[(size_t)(bm + rl) * DD + col];
            float2 rb = *(const float2*)&res[(size_t)(bm + rl + 8) * DD + col];
            acc[mt][nt][0] += bb.x + ra.x;
            acc[mt][nt][1] += bb.y + ra.y;
            acc[mt][nt][2] += bb.x + rb.x;
            acc[mt][nt][3] += bb.y + rb.y;
            rs[mt * 2 + 0] += acc[mt][nt][0] + acc[mt][nt][1];
            rq[mt * 2 + 0] += acc[mt][nt][0] * acc[mt][nt][0] + acc[mt][nt][1] * acc[mt][nt][1];
            rs[mt * 2 + 1] += acc[mt][nt][2] + acc[mt][nt][3];
            rq[mt * 2 + 1] += acc[mt][nt][2] * acc[mt][nt][2] + acc[mt][nt][3] * acc[mt][nt][3];
        }
    }
#pragma unroll
    for (int j = 0; j < 4; j++) {
        rs[j] += __shfl_xor_sync(0xffffffffu, rs[j], 1);
        rs[j] += __shfl_xor_sync(0xffffffffu, rs[j], 2);
        rq[j] += __shfl_xor_sync(0xffffffffu, rq[j], 1);
        rq[j] += __shfl_xor_sync(0xffffffffu, rq[j], 2);
    }
    if (lt == 0) {
#pragma unroll
        for (int mt = 0; mt < 2; mt++)
#pragma unroll
            for (int i = 0; i < 2; i++) {
                int row = wm * 32 + mt * 16 + lg + i * 8;
                partS[wn * 64 + row] = rs[mt * 2 + i];
                partQ[wn * 64 + row] = rq[mt * 2 + i];
            }
    }
    __syncthreads();

#pragma unroll
    for (int mt = 0; mt < 2; mt++) {
        int rl = wm * 32 + mt * 16 + lg;
        float mu[2], inv[2];
#pragma unroll
        for (int i = 0; i < 2; i++) {
            int row = rl + i * 8;
            float S = partS[row] + partS[64 + row] + partS[128 + row] + partS[192 + row];
            float Q = partQ[row] + partQ[64 + row] + partQ[128 + row] + partQ[192 + row];
            mu[i] = S * (1.0f / DD);
            float var = Q * (1.0f / DD) - mu[i] * mu[i];
            inv[i] = rsqrtf(var + 1e-5f);
        }
#pragma unroll
        for (int nt = 0; nt < 8; nt++) {
            int col = wn * 64 + nt * 8 + (lt << 1);
            float2 wv = *(const float2*)&lnw[col];
            float2 bv = *(const float2*)&lnb[col];
            float y0 = f2tf_f((acc[mt][nt][0] - mu[0]) * inv[0] * wv.x + bv.x);
            float y1 = f2tf_f((acc[mt][nt][1] - mu[0]) * inv[0] * wv.y + bv.y);
            float y2 = f2tf_f((acc[mt][nt][2] - mu[1]) * inv[1] * wv.x + bv.x);
            float y3 = f2tf_f((acc[mt][nt][3] - mu[1]) * inv[1] * wv.y + bv.y);
            *(float2*)&Y[(size_t)(bm + rl) * DD + col] = make_float2(y0, y1);
            *(float2*)&Y[(size_t)(bm + rl + 8) * DD + col] = make_float2(y2, y3);
        }
    }
}

// ---------------- CSR build (once per launch) ----------------
__global__ void csr_zero_kernel() {
    int i = blockIdx.x * blockDim.x + threadIdx.x;
    if (i < NN) g_deg[i] = 0;
}

__global__ void csr_hist_kernel(const int* __restrict__ dst, int E, int Etot) {
    int e = blockIdx.x * blockDim.x + threadIdx.x;
    if (e >= Etot) return;
    int d = (e < E) ? dst[e] : (e - E);
    atomicAdd(&g_deg[d], 1);
}

__global__ void __launch_bounds__(1024) csr_scan_kernel() {
    __shared__ int ts[1024];
    int t = threadIdx.x;
    int base = t * 8;
    int local[8];
    int s = 0;
#pragma unroll
    for (int j = 0; j < 8; j++) { local[j] = s; s += g_deg[base + j]; }
    ts[t] = s;
    __syncthreads();
    for (int off = 1; off < 1024; off <<= 1) {
        int v = (t >= off) ? ts[t - off] : 0;
        __syncthreads();
        ts[t] += v;
        __syncthreads();
    }
    int prefix = (t == 0) ? 0 : ts[t - 1];
#pragma unroll
    for (int j = 0; j < 8; j++) {
        int o = prefix + local[j];
        g_off[base + j] = o;
        g_pos[base + j] = o;
    }
    if (t == 1023) g_off[NN] = ts[1023];
}

__global__ void csr_fill_kernel(const int* __restrict__ src, const int* __restrict__ dst,
                                int E, int Etot) {
    int e = blockIdx.x * blockDim.x + threadIdx.x;
    if (e >= Etot) return;
    int s, d;
    if (e < E) { s = src[e]; d = dst[e]; } else { s = d = e - E; }
    int p = atomicAdd(&g_pos[d], 1);
    g_esrc[p] = s;
    g_edst[p] = d;
}

// ---------------- GAT kernels ----------------
__global__ void gat_coef_kernel(const float* __restrict__ hl,
                                const float* __restrict__ atts,
                                const float* __restrict__ attd,
                                float* __restrict__ as_, float* __restrict__ ad_)
{
    int t = blockIdx.x * blockDim.x + threadIdx.x;
    if (t >= NN * HH) return;
    int n = t >> 3, h = t & 7;
    const float4* hp = reinterpret_cast<const float4*>(&hl[(size_t)n * DD + h * 32]);
    const float4* sp = reinterpret_cast<const float4*>(&atts[h * 32]);
    const float4* dp = reinterpret_cast<const float4*>(&attd[h * 32]);
    float ss = 0.f, dd = 0.f;
#pragma unroll
    for (int w = 0; w < 8; w++) {
        float4 hv = hp[w], sv = sp[w], dv = dp[w];
        ss += hv.x * sv.x + hv.y * sv.y + hv.z * sv.z + hv.w * sv.w;
        dd += hv.x * dv.x + hv.y * dv.y + hv.z * dv.z + hv.w * dv.w;
    }
    as_[t] = ss;
    ad_[t] = dd;
}

__global__ void gat_edge_p_kernel(int Etot,
                                  const float* __restrict__ as_,
                                  const float* __restrict__ ad_,
                                  float* __restrict__ pe)
{
    int i = blockIdx.x * blockDim.x + threadIdx.x;
    if (i >= Etot) return;
    int s = g_esrc[i], d = g_edst[i];
    float4 s0 = *(const float4*)&as_[s * 8];
    float4 s1 = *(const float4*)&as_[s * 8 + 4];
    float4 d0 = *(const float4*)&ad_[d * 8];
    float4 d1 = *(const float4*)&ad_[d * 8 + 4];
    float a[8] = {s0.x + d0.x, s0.y + d0.y, s0.z + d0.z, s0.w + d0.w,
                  s1.x + d1.x, s1.y + d1.y, s1.z + d1.z, s1.w + d1.w};
#pragma unroll
    for (int h = 0; h < 8; h++) {
        float t = a[h];
        t = (t > 0.f) ? t : 0.2f * t;
        a[h] = __expf(t);
    }
    *(float4*)&pe[(size_t)i * 8]     = make_float4(a[0], a[1], a[2], a[3]);
    *(float4*)&pe[(size_t)i * 8 + 4] = make_float4(a[4], a[5], a[6], a[7]);
}

__global__ void __launch_bounds__(256) gat_gather_kernel(
    const float* __restrict__ hl, const float* __restrict__ pe,
    const float* __restrict__ bias, float* __restrict__ out)
{
    const int d = blockIdx.x;
    const int h = threadIdx.x >> 5, lane = threadIdx.x & 31;
    const int beg = g_off[d], end = g_off[d + 1];
    const int hc = h * 32 + lane;

    float acc0 = 0.f, acc1 = 0.f, acc2 = 0.f, acc3 = 0.f;
    float ss = 0.f;
    int i = beg;
    for (; i + 4 <= end; i += 4) {
        int s0 = g_esrc[i], s1 = g_esrc[i + 1], s2 = g_esrc[i + 2], s3 = g_esrc[i + 3];
        float p0 = pe[(size_t)i * 8 + h];
        float p1 = pe[(size_t)(i + 1) * 8 + h];
        float p2 = pe[(size_t)(i + 2) * 8 + h];
        float p3 = pe[(size_t)(i + 3) * 8 + h];
        float v0 = hl[(size_t)s0 * DD + hc];
        float v1 = hl[(size_t)s1 * DD + hc];
        float v2 = hl[(size_t)s2 * DD + hc];
        float v3 = hl[(size_t)s3 * DD + hc];
        ss += (p0 + p1) + (p2 + p3);
        acc0 = fmaf(p0, v0, acc0);
        acc1 = fmaf(p1, v1, acc1);
        acc2 = fmaf(p2, v2, acc2);
        acc3 = fmaf(p3, v3, acc3);
    }
    for (; i < end; i++) {
        int s0 = g_esrc[i];
        float p0 = pe[(size_t)i * 8 + h];
        ss += p0;
        acc0 = fmaf(p0, hl[(size_t)s0 * DD + hc], acc0);
    }
    float acc = (acc0 + acc1) + (acc2 + acc3);
    out[(size_t)d * DD + hc] = f2tf_f(fmaxf(acc / ss + bias[hc], 0.f));
}

// ---------------- MMA flash-attention ----------------
__global__ void __launch_bounds__(128) attn_mma_kernel(const float* __restrict__ qkv,
                                                       float* __restrict__ out)
{
    __shared__ __align__(16) float Qs[64][36];
    __shared__ __align__(16) float Ks[64][36];
    __shared__ __align__(16) float Vt[32][68];
    __shared__ __align__(16) float Ps[64][68];

    const int bh = blockIdx.x, b = bh >> 3, h = bh & 7;
    const int qt = blockIdx.y;
    const int tid = threadIdx.x;
    const int warp = tid >> 5, lane = tid & 31;
    const int lg = lane >> 2, lt = lane & 3;
    const float* base = qkv + (size_t)b * LL * 768;
    const float scale = 0.17677669529663687f;

#pragma unroll
    for (int i = 0; i < 4; i++) {
        int idx = tid + i * 128;
        int row = idx >> 3, c4 = (idx & 7) << 2;
        float4 v = *(const float4*)(base + (size_t)(qt * 64 + row) * 768 + h * 32 + c4);
        Qs[row][c4 + 0] = f2tf_f(v.x * scale);
        Qs[row][c4 + 1] = f2tf_f(v.y * scale);
        Qs[row][c4 + 2] = f2tf_f(v.z * scale);
        Qs[row][c4 + 3] = f2tf_f(v.w * scale);
    }

    float m0 = -1e30f, m1 = -1e30f, l0 = 0.f, l1 = 0.f;
    float o[4][4];
#pragma unroll
    for (int nt = 0; nt < 4; nt++)
#pragma unroll
        for (int r = 0; r < 4; r++) o[nt][r] = 0.f;

    const int r0 = warp * 16 + lg;

    for (int kt = 0; kt < 16; kt++) {
        __syncthreads();
#pragma unroll
        for (int i = 0; i < 4; i++) {
            int idx = tid + i * 128;
            int row = idx >> 3, c4 = (idx & 7) << 2;
            const float* kp = base + (size_t)(kt * 64 + row) * 768 + 256 + h * 32 + c4;
            float4 kv = *(const float4*)kp;
            Ks[row][c4 + 0] = kv.x; Ks[row][c4 + 1] = kv.y;
            Ks[row][c4 + 2] = kv.z; Ks[row][c4 + 3] = kv.w;
            float4 vv = *(const float4*)(kp + 256);
            Vt[c4 + 0][row] = vv.x; Vt[c4 + 1][row] = vv.y;
            Vt[c4 + 2][row] = vv.z; Vt[c4 + 3][row] = vv.w;
        }
        __syncthreads();

        float s[8][4];
#pragma unroll
        for (int nt = 0; nt < 8; nt++)
#pragma unroll
            for (int r = 0; r < 4; r++) s[nt][r] = 0.f;
#pragma unroll
        for (int kk = 0; kk < 4; kk++) {
            const int c = kk * 8 + lt;
            unsigned a[4];
            a[0] = __float_as_uint(Qs[r0][c]);
            a[1] = __float_as_uint(Qs[r0 + 8][c]);
            a[2] = __float_as_uint(Qs[r0][c + 4]);
            a[3] = __float_as_uint(Qs[r0 + 8][c + 4]);
#pragma unroll
            for (int nt = 0; nt < 8; nt++) {
                unsigned bb[2];
                bb[0] = __float_as_uint(Ks[nt * 8 + lg][c]);
                bb[1] = __float_as_uint(Ks[nt * 8 + lg][c + 4]);
                mma8(s[nt], a, bb);
            }
        }

        float mx0 = -1e30f, mx1 = -1e30f;
#pragma unroll
        for (int nt = 0; nt < 8; nt++) {
            mx0 = fmaxf(mx0, fmaxf(s[nt][0], s[nt][1]));
            mx1 = fmaxf(mx1, fmaxf(s[nt][2], s[nt][3]));
        }
        mx0 = fmaxf(mx0, __shfl_xor_sync(0xffffffffu, mx0, 1));
        mx0 = fmaxf(mx0, __shfl_xor_sync(0xffffffffu, mx0, 2));
        mx1 = fmaxf(mx1, __shfl_xor_sync(0xffffffffu, mx1, 1));
        mx1 = fmaxf(mx1, __shfl_xor_sync(0xffffffffu, mx1, 2));
        float nm0 = fmaxf(m0, mx0), nm1 = fmaxf(m1, mx1);
        float c0 = __expf(m0 - nm0), c1 = __expf(m1 - nm1);
        m0 = nm0; m1 = nm1;

        float ps0 = 0.f, ps1 = 0.f;
#pragma unroll
        for (int nt = 0; nt < 8; nt++) {
            float p0 = __expf(s[nt][0] - m0);
            float p1 = __expf(s[nt][1] - m0);
            float p2 = __expf(s[nt][2] - m1);
            float p3 = __expf(s[nt][3] - m1);
            ps0 += p0 + p1;
            ps1 += p2 + p3;
            int col = nt * 8 + (lt << 1);
            Ps[r0][col]     = p0;
            Ps[r0][col + 1] = p1;
            Ps[r0 + 8][col]     = p2;
            Ps[r0 + 8][col + 1] = p3;
        }
        ps0 += __shfl_xor_sync(0xffffffffu, ps0, 1);
        ps0 += __shfl_xor_sync(0xffffffffu, ps0, 2);
        ps1 += __shfl_xor_sync(0xffffffffu, ps1, 1);
        ps1 += __shfl_xor_sync(0xffffffffu, ps1, 2);
        l0 = l0 * c0 + ps0;
        l1 = l1 * c1 + ps1;
#pragma unroll
        for (int nt = 0; nt < 4; nt++) {
            o[nt][0] *= c0; o[nt][1] *= c0;
            o[nt][2] *= c1; o[nt][3] *= c1;
        }
        __syncwarp();

#pragma unroll
        for (int kk = 0; kk < 8; kk++) {
            const int c = kk * 8 + lt;
            unsigned a[4];
            a[0] = __float_as_uint(Ps[r0][c]);
            a[1] = __float_as_uint(Ps[r0 + 8][c]);
            a[2] = __float_as_uint(Ps[r0][c + 4]);
            a[3] = __float_as_uint(Ps[r0 + 8][c + 4]);
#pragma unroll
            for (int nt = 0; nt < 4; nt++) {
                unsigned bb[2];
                bb[0] = __float_as_uint(Vt[nt * 8 + lg][c]);
                bb[1] = __float_as_uint(Vt[nt * 8 + lg][c + 4]);
                mma8(o[nt], a, bb);
            }
        }
    }

    float inv0 = 1.0f / l0, inv1 = 1.0f / l1;
    int q0 = qt * 64 + r0;
    float* op = out + (size_t)(b * LL + q0) * DD + h * 32;
#pragma unroll
    for (int nt = 0; nt < 4; nt++) {
        int col = nt * 8 + (lt << 1);
        *(float2*)(op + col) = make_float2(f2tf_f(o[nt][0] * inv0), f2tf_f(o[nt][1] * inv0));
        *(float2*)(op + 8 * DD + col) = make_float2(f2tf_f(o[nt][2] * inv1), f2tf_f(o[nt][3] * inv1));
    }
}

// ---------------- final prediction ----------------
__global__ void __launch_bounds__(256) pred_kernel(
    const float* __restrict__ x, const float* __restrict__ pw,
    const float* __restrict__ pb, float* __restrict__ out)
{
    int n = blockIdx.x * 8 + (threadIdx.x >> 5);
    int lane = threadIdx.x & 31;
    const float* xr = x + (size_t)n * DD;
    float xv[8];
#pragma unroll
    for (int k = 0; k < 8; k++) xv[k] = xr[lane + 32 * k];
    float a0 = 0.f, a1 = 0.f, a2 = 0.f;
#pragma unroll
    for (int k = 0; k < 8; k++) {
        int c = lane + 32 * k;
        a0 += xv[k] * pw[0 * DD + c];
        a1 += xv[k] * pw[1 * DD + c];
        a2 += xv[k] * pw[2 * DD + c];
    }
#pragma unroll
    for (int o = 16; o; o >>= 1) {
        a0 += __shfl_xor_sync(0xffffffffu, a0, o);
        a1 += __shfl_xor_sync(0xffffffffu, a1, o);
        a2 += __shfl_xor_sync(0xffffffffu, a2, o);
    }
    if (lane == 0) {
        out[n * 3 + 0] = a0 + pb[0];
        out[n * 3 + 1] = a1 + pb[1];
        out[n * 3 + 2] = a2 + pb[2];
    }
}

// ---------------- host orchestration ----------------
extern "C" void kernel_launch(void* const* d_in, const int* in_sizes, int n_in,
                              void* d_out, int out_size)
{
    const float* x        = (const float*)d_in[0];
    const int*   ei       = (const int*)  d_in[1];
    const float* gat_W0   = (const float*)d_in[3];
    const float* gat_W12  = (const float*)d_in[4];
    const float* att_src  = (const float*)d_in[5];
    const float* att_dst  = (const float*)d_in[6];
    const float* gat_bias = (const float*)d_in[7];
    const float* qkv_w    = (const float*)d_in[8];
    const float* qkv_b    = (const float*)d_in[9];
    const float* out_w    = (const float*)d_in[10];
    const float* out_b    = (const float*)d_in[11];
    const float* ln1_w    = (const float*)d_in[12];
    const float* ln1_b    = (const float*)d_in[13];
    const float* ln2_w    = (const float*)d_in[14];
    const float* ln2_b    = (const float*)d_in[15];
    const float* ff1_w    = (const float*)d_in[16];
    const float* ff1_b    = (const float*)d_in[17];
    const float* ff2_w    = (const float*)d_in[18];
    const float* ff2_b    = (const float*)d_in[19];
    const float* pred_w   = (const float*)d_in[20];
    const float* pred_b   = (const float*)d_in[21];

    const int E = in_sizes[1] / 2;
    const int Etot = E + NN;
    const int* src = ei;
    const int* dst = ei + E;

    float *hl, *h0, *h1, *as_, *ad_, *pe, *qkv, *attn, *ff;
    cudaGetSymbolAddress((void**)&hl,   g_hl);
    cudaGetSymbolAddress((void**)&h0,   g_h0);
    cudaGetSymbolAddress((void**)&h1,   g_h1);
    cudaGetSymbolAddress((void**)&as_,  g_as);
    cudaGetSymbolAddress((void**)&ad_,  g_ad);
    cudaGetSymbolAddress((void**)&pe,   g_pe);
    cudaGetSymbolAddress((void**)&qkv,  g_qkv);
    cudaGetSymbolAddress((void**)&attn, g_attn);
    cudaGetSymbolAddress((void**)&ff,   g_ff);

    cudaFuncSetAttribute(tgemm_kernel<0>, cudaFuncAttributeMaxDynamicSharedMemorySize, TG_SMEM3);
    cudaFuncSetAttribute(tgemm_kernel<1>, cudaFuncAttributeMaxDynamicSharedMemorySize, TG_SMEM3);
    cudaFuncSetAttribute(tgemm_kernel<2>, cudaFuncAttributeMaxDynamicSharedMemorySize, TG_SMEM3);
    cudaFuncSetAttribute(tgemm_ln_kernel, cudaFuncAttributeMaxDynamicSharedMemorySize, TL_SMEM3);

    const int eb = (Etot + 255) / 256;

    // CSR build (once)
    csr_zero_kernel<<<(NN + 255) / 256, 256>>>();
    csr_hist_kernel<<<eb, 256>>>(dst, E, Etot);
    csr_scan_kernel<<<1, 1024>>>();
    csr_fill_kernel<<<eb, 256>>>(src, dst, E, Etot);

    auto gat_layer = [&](const float* in, int Din, const float* W,
                         const float* atts, const float* attd, const float* bias,
                         float* outp) {
        tgemm_kernel<0><<<dim3(DD / 128, NN / 128), 256, TG_SMEM3>>>(in, W, nullptr, hl, NN, DD, Din);
        gat_coef_kernel<<<(NN * HH) / 256, 256>>>(hl, atts, attd, as_, ad_);
        gat_edge_p_kernel<<<eb, 256>>>(Etot, as_, ad_, pe);
        gat_gather_kernel<<<NN, 256>>>(hl, pe, bias, outp);
    };

    gat_layer(x,  INC, gat_W0,            att_src,           att_dst,           gat_bias,          h0);
    gat_layer(h0, DD,  gat_W12,           att_src + HH * CC, att_dst + HH * CC, gat_bias + DD,     h1);
    gat_layer(h1, DD,  gat_W12 + DD * DD, att_src + 2*HH*CC, att_dst + 2*HH*CC, gat_bias + 2 * DD, h0);

    for (int l = 0; l < 2; l++) {
        const float* qw  = qkv_w + (size_t)l * 3 * DD * DD;
        const float* qb  = qkv_b + l * 3 * DD;
        const float* ow  = out_w + (size_t)l * DD * DD;
        const float* ob  = out_b + l * DD;
        const float* l1w = ln1_w + l * DD, * l1b = ln1_b + l * DD;
        const float* l2w = ln2_w + l * DD, * l2b = ln2_b + l * DD;
        const float* f1w = ff1_w + (size_t)l * DFF * DD;
        const float* f1b = ff1_b + l * DFF;
        const float* f2w = ff2_w + (size_t)l * DD * DFF;
        const float* f2b = ff2_b + l * DD;

        tgemm_kernel<1><<<dim3(3 * DD / 128, NN / 128), 256, TG_SMEM3>>>(h0, qw, qb, qkv, NN, 3 * DD, DD);
        attn_mma_kernel<<<dim3(BB * HH, LL / 64), 128>>>(qkv, attn);
        // h1 = LN(h0 + attn@ow^T + ob)
        tgemm_ln_kernel<<<dim3(1, NN / 64), 256, TL_SMEM3>>>(attn, ow, ob, h0, l1w, l1b, h1, NN, DD);
        tgemm_kernel<2><<<dim3(DFF / 128, NN / 128), 256, TG_SMEM3>>>(h1, f1w, f1b, ff, NN, DFF, DD);
        // h0 = LN(h1 + ff@f2w^T + f2b)
        tgemm_ln_kernel<<<dim3(1, NN / 64), 256, TL_SMEM3>>>(ff, f2w, f2b, h1, l2w, l2b, h0, NN, DFF);
    }

    pred_kernel<<<NN / 8, 256>>>(h0, pred_w, pred_b, (float*)d_out);
}